// round 15
// baseline (speedup 1.0000x reference)
#include <cuda_runtime.h>
#include <cuda_bf16.h>
#include <math.h>
#include <stdint.h>

// ---------------- problem constants ----------------
#define B_   8
#define L_   512
#define D_   768
#define NL_  12
#define E_   8192
#define H_   12
#define DH_  64
#define DF_  3072
#define M_   4096       // B_*L_
#define TD_  2304       // 3*D_
#define BH_  96         // B_*H_

// ---------------- mma-gemm tile config ----------------
#define TM_T 128
#define TK_T 64
#define GRST 72                        // smem row stride (bf16), 64 elems + 8 pad
#define A_TILE_B (TM_T * GRST * 2)     // 18432 bytes per array per stage
#define SMEM_MMA(TNT) (4 * A_TILE_B + 4 * (TNT) * GRST * 2)

// ---------------- fused attention smem layout (bytes) ----------------
#define KRST 72
#define PSTR 520     // P row stride (bf16)
#define VSTR 264     // V chunk row stride (bf16)
#define PH_OFF  0
#define PL_OFF  66560
#define VH_OFF  133120
#define VL_OFF  166912
#define QH_OFF  200704
#define QL_OFF  209920
#define RED_OFF 219136
#define FIN_OFF 221184
#define SMEM_ATT 221440
#define KH_OFF  0
#define KL_OFF  73728

// ---------------- scratch (static device memory) ----------------
__device__ float g_h  [M_ * D_];
__device__ float g_h1 [M_ * D_];
__device__ float g_y  [M_ * D_];
__device__ float g_g  [M_ * D_];
__device__ float g_dinv[B_ * L_];
__device__ float g_pairC[2 * M_ * D_];
__device__ float g_bias2[NL_ * 2 * D_];
// CSR for sparse GCN aggregation
__device__ int   g_cnt [B_ * L_];
__device__ int   g_start[B_ * (L_ + 1)];
__device__ int   g_cur [B_ * L_];
__device__ int   g_esrc[B_ * E_];
__device__ float g_ew  [B_ * E_];
// bf16 hi/lo pairs
__device__ __nv_bfloat16 g_hh [M_ * D_],  g_hl [M_ * D_];
__device__ __nv_bfloat16 g_qkvh[M_ * TD_], g_qkvl[M_ * TD_];
__device__ __nv_bfloat16 g_vth[BH_ * DH_ * L_], g_vtl[BH_ * DH_ * L_];
__device__ __nv_bfloat16 g_ctxh[M_ * D_], g_ctxl[M_ * D_];
__device__ __nv_bfloat16 g_pairAh[2 * M_ * D_], g_pairAl[2 * M_ * D_];
__device__ __nv_bfloat16 g_pairCh[2 * M_ * D_], g_pairCl[2 * M_ * D_];
__device__ __nv_bfloat16 g_xh [M_ * D_],  g_xl [M_ * D_];
__device__ __nv_bfloat16 g_yh [M_ * D_],  g_yl [M_ * D_];
__device__ __nv_bfloat16 g_ggh[M_ * D_],  g_ggl[M_ * D_];
__device__ __nv_bfloat16 g_midh[M_ * DF_], g_midl[M_ * DF_];
__device__ __nv_bfloat16 g_wTh[120324096], g_wTl[120324096];

#define OFF_QKV 0L
#define OFF_WO  21233664L
#define OFF_M1  28311552L
#define OFF_C1  35389440L
#define OFF_C2  42467328L
#define OFF_M2  49545216L
#define OFF_M3  56623104L
#define OFF_INT 63700992L
#define OFF_OUT 92012544L

// ---------------- helpers ----------------
__device__ __forceinline__ uint32_t smem_u32(const void* p) {
    uint32_t a;
    asm("{ .reg .u64 t; cvta.to.shared.u64 t, %1; cvt.u32.u64 %0, t; }" : "=r"(a) : "l"(p));
    return a;
}
__device__ __forceinline__ float gelu_f(float v) {
    return 0.5f * v * (1.0f + erff(v * 0.7071067811865475f));
}
__device__ __forceinline__ void cp16(uint32_t dst, const void* src) {
    asm volatile("cp.async.cg.shared.global [%0], [%1], 16;" :: "r"(dst), "l"(src));
}
#define CP_COMMIT() asm volatile("cp.async.commit_group;" ::: "memory")
#define CP_WAIT(n)  asm volatile("cp.async.wait_group %0;" :: "n"(n) : "memory")

#define LDSM_X4(r0, r1, r2, r3, addr) \
    asm volatile("ldmatrix.sync.aligned.m8n8.x4.shared.b16 {%0,%1,%2,%3}, [%4];" \
        : "=r"(r0), "=r"(r1), "=r"(r2), "=r"(r3) : "r"(addr))

__device__ __forceinline__ void split2(float vx, float vy, uint32_t& hi, uint32_t& lo) {
    __nv_bfloat162 h = __floats2bfloat162_rn(vx, vy);
    float rx = vx - __bfloat162float(h.x);
    float ry = vy - __bfloat162float(h.y);
    __nv_bfloat162 l = __floats2bfloat162_rn(rx, ry);
    hi = *reinterpret_cast<uint32_t*>(&h);
    lo = *reinterpret_cast<uint32_t*>(&l);
}

__device__ __forceinline__ void mma_bf16(float c[4], const uint32_t a[4], uint32_t b0, uint32_t b1) {
    asm volatile(
        "mma.sync.aligned.m16n8k16.row.col.f32.bf16.bf16.f32 "
        "{%0,%1,%2,%3}, {%4,%5,%6,%7}, {%8,%9}, {%0,%1,%2,%3};"
        : "+f"(c[0]), "+f"(c[1]), "+f"(c[2]), "+f"(c[3])
        : "r"(a[0]), "r"(a[1]), "r"(a[2]), "r"(a[3]), "r"(b0), "r"(b1));
}

// ---------------- bf16x3 mma.sync GEMM (TK=64 chunks, templated tile N) ----------------
// Vh/Vl non-null => qkv mode: cols >= 2*D_ are written TRANSPOSED into vt arrays
template <int EPI, int TNT>
__global__ __launch_bounds__(256, 1)
void mma_gemm(const __nv_bfloat16* __restrict__ Ah, const __nv_bfloat16* __restrict__ Al,
              const __nv_bfloat16* __restrict__ Bh, const __nv_bfloat16* __restrict__ Bl,
              const float* __restrict__ bias, const float* __restrict__ add,
              float* __restrict__ C, __nv_bfloat16* __restrict__ Ch, __nv_bfloat16* __restrict__ Cl,
              __nv_bfloat16* __restrict__ Vh, __nv_bfloat16* __restrict__ Vl,
              int K, int N, long sA, long sB, long sC, long sBias)
{
    constexpr int WNT = TNT / 4;
    constexpr int NTI = WNT / 8;
    constexpr int PB  = WNT / 16;
    constexpr int BCP = TNT / 32;
    constexpr int B_TILE_B = TNT * GRST * 2;

    extern __shared__ char smc[];
    const uint32_t sAh_u = smem_u32(smc);
    const uint32_t sAl_u = sAh_u + 2 * A_TILE_B;
    const uint32_t sBh_u = sAh_u + 4 * A_TILE_B;
    const uint32_t sBl_u = sBh_u + 2 * B_TILE_B;

    const int tid = threadIdx.x;
    const long z = blockIdx.z;
    Ah += z * sA; Al += z * sA;
    Bh += z * sB; Bl += z * sB;
    if (C)  C  += z * sC;
    if (Ch) { Ch += z * sC; Cl += z * sC; }
    const float* biasp = bias ? bias + z * sBias : (const float*)0;
    const float* addp = (EPI == 1 || EPI == 3) ? add + z * sC : (const float*)0;

    const int m0 = blockIdx.y * TM_T;
    const int n0 = blockIdx.x * TNT;
    const int wid = tid >> 5, lane = tid & 31;
    const int wm = wid >> 2, wn = wid & 3;
    const int gid = lane >> 2, tq = lane & 3;

    const uint32_t a_off = (uint32_t)(((wm * 64 + (lane & 15)) * GRST + (lane >> 4) * 8) * 2);
    const uint32_t b_off = (uint32_t)(((wn * WNT + (lane & 7) + (lane >> 4) * 8) * GRST
                                      + ((lane >> 3) & 1) * 8) * 2);

    float c[4][NTI][4];
    #pragma unroll
    for (int mt = 0; mt < 4; mt++)
        #pragma unroll
        for (int nt = 0; nt < NTI; nt++)
            #pragma unroll
            for (int i = 0; i < 4; i++) c[mt][nt][i] = 0.f;

    const int nck = K / TK_T;

    auto prefetch = [&](int s, int k0) {
        #pragma unroll
        for (int i = 0; i < 4; i++) {
            int t = tid + i * 256;
            int r = t >> 3, g = t & 7;
            cp16(sAh_u + s * A_TILE_B + (r * GRST + g * 8) * 2,
                 Ah + (long)(m0 + r) * K + k0 + g * 8);
        }
        #pragma unroll
        for (int i = 0; i < 4; i++) {
            int t = tid + i * 256;
            int r = t >> 3, g = t & 7;
            cp16(sAl_u + s * A_TILE_B + (r * GRST + g * 8) * 2,
                 Al + (long)(m0 + r) * K + k0 + g * 8);
        }
        #pragma unroll
        for (int i = 0; i < BCP; i++) {
            int t = tid + i * 256;
            int r = t >> 3, g = t & 7;
            cp16(sBh_u + s * B_TILE_B + (r * GRST + g * 8) * 2,
                 Bh + (long)(n0 + r) * K + k0 + g * 8);
        }
        #pragma unroll
        for (int i = 0; i < BCP; i++) {
            int t = tid + i * 256;
            int r = t >> 3, g = t & 7;
            cp16(sBl_u + s * B_TILE_B + (r * GRST + g * 8) * 2,
                 Bl + (long)(n0 + r) * K + k0 + g * 8);
        }
        CP_COMMIT();
    };

    prefetch(0, 0);

    for (int ck = 0; ck < nck; ck++) {
        if (ck + 1 < nck) { prefetch((ck + 1) & 1, (ck + 1) * TK_T); CP_WAIT(1); }
        else              { CP_WAIT(0); }
        __syncthreads();

        const int st = ck & 1;
        const uint32_t aH = sAh_u + st * A_TILE_B + a_off;
        const uint32_t aL = sAl_u + st * A_TILE_B + a_off;
        const uint32_t bH = sBh_u + st * B_TILE_B + b_off;
        const uint32_t bL = sBl_u + st * B_TILE_B + b_off;

        #pragma unroll
        for (int kk = 0; kk < 4; kk++) {
            const uint32_t ko = kk * 32;
            uint32_t Bhr[PB * 4], Blr[PB * 4];
            #pragma unroll
            for (int p = 0; p < PB; p++) {
                LDSM_X4(Bhr[p*4+0], Bhr[p*4+1], Bhr[p*4+2], Bhr[p*4+3], bH + p * (16*GRST*2) + ko);
                LDSM_X4(Blr[p*4+0], Blr[p*4+1], Blr[p*4+2], Blr[p*4+3], bL + p * (16*GRST*2) + ko);
            }
            #pragma unroll
            for (int mt = 0; mt < 4; mt++) {
                uint32_t ah[4], al[4];
                LDSM_X4(ah[0], ah[1], ah[2], ah[3], aH + mt * (16*GRST*2) + ko);
                LDSM_X4(al[0], al[1], al[2], al[3], aL + mt * (16*GRST*2) + ko);
                #pragma unroll
                for (int nt = 0; nt < NTI; nt++) {
                    const int bi = (nt >> 1) * 4 + (nt & 1) * 2;
                    mma_bf16(c[mt][nt], al, Bhr[bi], Bhr[bi+1]);
                }
                #pragma unroll
                for (int nt = 0; nt < NTI; nt++) {
                    const int bi = (nt >> 1) * 4 + (nt & 1) * 2;
                    mma_bf16(c[mt][nt], ah, Blr[bi], Blr[bi+1]);
                }
                #pragma unroll
                for (int nt = 0; nt < NTI; nt++) {
                    const int bi = (nt >> 1) * 4 + (nt & 1) * 2;
                    mma_bf16(c[mt][nt], ah, Bhr[bi], Bhr[bi+1]);
                }
            }
        }
        __syncthreads();
    }

    #pragma unroll
    for (int mt = 0; mt < 4; mt++) {
        const int r0 = m0 + wm * 64 + mt * 16 + gid;
        #pragma unroll
        for (int nt = 0; nt < NTI; nt++) {
            const int col = n0 + wn * WNT + nt * 8 + tq * 2;
            float bx = 0.f, by = 0.f;
            if (biasp) { bx = biasp[col]; by = biasp[col + 1]; }
            #pragma unroll
            for (int half = 0; half < 2; half++) {
                const int r = r0 + half * 8;
                float vx = c[mt][nt][half * 2 + 0] + bx;
                float vy = c[mt][nt][half * 2 + 1] + by;
                if (EPI == 2 || EPI == 3) { vx = gelu_f(vx); vy = gelu_f(vy); }
                if (EPI == 1 || EPI == 3) {
                    const float* ap = &addp[(long)r * N + col];
                    vx += ap[0]; vy += ap[1];
                }
                if (C) *(float2*)&C[(long)r * N + col] = make_float2(vx, vy);
                if (Vh && col >= 2 * D_) {
                    // transposed V write: row r=(b,s), feature hf -> vt[(b*768+hf)*512+s]
                    const int bb = r >> 9, ss = r & 511;
                    const int hf = col - 2 * D_;
                    const long d0 = ((long)(bb * 768 + hf) << 9) + ss;
                    __nv_bfloat16 hx = __float2bfloat16_rn(vx);
                    __nv_bfloat16 hy = __float2bfloat16_rn(vy);
                    Vh[d0]       = hx;
                    Vh[d0 + 512] = hy;
                    Vl[d0]       = __float2bfloat16_rn(vx - __bfloat162float(hx));
                    Vl[d0 + 512] = __float2bfloat16_rn(vy - __bfloat162float(hy));
                } else if (Ch) {
                    uint32_t hi, lo;
                    split2(vx, vy, hi, lo);
                    *(uint32_t*)&Ch[(long)r * N + col] = hi;
                    *(uint32_t*)&Cl[(long)r * N + col] = lo;
                }
            }
        }
    }
}

// ---------------- fused attention: S=softmax(QK^T/8) in regs -> P in smem -> ctx=P@V ----
__global__ __launch_bounds__(256, 1)
void attn_fused(const __nv_bfloat16* __restrict__ qkvh,
                const __nv_bfloat16* __restrict__ qkvl,
                const __nv_bfloat16* __restrict__ vth, const __nv_bfloat16* __restrict__ vtl,
                __nv_bfloat16* __restrict__ ctxh, __nv_bfloat16* __restrict__ ctxl)
{
    extern __shared__ char smc[];
    const uint32_t sb = smem_u32(smc);
    float* red = (float*)(smc + RED_OFF);
    float* fin = (float*)(smc + FIN_OFF);

    const int bh = blockIdx.x;
    const int b = bh / H_, head = bh % H_;
    const int q0 = blockIdx.y * 64;
    const int tid = threadIdx.x;
    const int wid = tid >> 5, lane = tid & 31;
    const int gid = lane >> 2, tq = lane & 3;

    const long qbase = (long)b * L_ * TD_ + head * DH_;

    #pragma unroll
    for (int i = 0; i < 16; i++) {
        int t = tid + i * 256;
        int r = t >> 3, g = t & 7;
        cp16(sb + KH_OFF + (r * KRST + g * 8) * 2, qkvh + qbase + (long)r * TD_ + D_ + g * 8);
    }
    #pragma unroll
    for (int i = 0; i < 16; i++) {
        int t = tid + i * 256;
        int r = t >> 3, g = t & 7;
        cp16(sb + KL_OFF + (r * KRST + g * 8) * 2, qkvl + qbase + (long)r * TD_ + D_ + g * 8);
    }
    #pragma unroll
    for (int i = 0; i < 2; i++) {
        int t = tid + i * 256;
        int r = t >> 3, g = t & 7;
        cp16(sb + QH_OFF + (r * KRST + g * 8) * 2, qkvh + qbase + (long)(q0 + r) * TD_ + g * 8);
    }
    #pragma unroll
    for (int i = 0; i < 2; i++) {
        int t = tid + i * 256;
        int r = t >> 3, g = t & 7;
        cp16(sb + QL_OFF + (r * KRST + g * 8) * 2, qkvl + qbase + (long)(q0 + r) * TD_ + g * 8);
    }
    CP_COMMIT();
    CP_WAIT(0);
    __syncthreads();

    const uint32_t a_off = (uint32_t)(((lane & 15) * KRST + (lane >> 4) * 8) * 2);
    const uint32_t b_off = (uint32_t)(((wid * 64 + (lane & 7) + (lane >> 4) * 8) * KRST
                                      + ((lane >> 3) & 1) * 8) * 2);

    float c[4][8][4];
    #pragma unroll
    for (int mt = 0; mt < 4; mt++)
        #pragma unroll
        for (int nt = 0; nt < 8; nt++)
            #pragma unroll
            for (int i = 0; i < 4; i++) c[mt][nt][i] = 0.f;

    #pragma unroll
    for (int kk = 0; kk < 4; kk++) {
        const uint32_t ko = kk * 32;
        uint32_t Bhr[16], Blr[16];
        #pragma unroll
        for (int p = 0; p < 4; p++) {
            LDSM_X4(Bhr[p*4+0], Bhr[p*4+1], Bhr[p*4+2], Bhr[p*4+3], sb + KH_OFF + b_off + p * (16*KRST*2) + ko);
            LDSM_X4(Blr[p*4+0], Blr[p*4+1], Blr[p*4+2], Blr[p*4+3], sb + KL_OFF + b_off + p * (16*KRST*2) + ko);
        }
        #pragma unroll
        for (int mt = 0; mt < 4; mt++) {
            uint32_t ah[4], al[4];
            LDSM_X4(ah[0], ah[1], ah[2], ah[3], sb + QH_OFF + a_off + mt * (16*KRST*2) + ko);
            LDSM_X4(al[0], al[1], al[2], al[3], sb + QL_OFF + a_off + mt * (16*KRST*2) + ko);
            #pragma unroll
            for (int nt = 0; nt < 8; nt++) {
                const int bi = (nt >> 1) * 4 + (nt & 1) * 2;
                mma_bf16(c[mt][nt], al, Bhr[bi], Bhr[bi+1]);
                mma_bf16(c[mt][nt], ah, Blr[bi], Blr[bi+1]);
                mma_bf16(c[mt][nt], ah, Bhr[bi], Bhr[bi+1]);
            }
        }
    }

    #pragma unroll
    for (int mt = 0; mt < 4; mt++) {
        #pragma unroll
        for (int half = 0; half < 2; half++) {
            float m = -3.0e38f;
            #pragma unroll
            for (int nt = 0; nt < 8; nt++) {
                #pragma unroll
                for (int j = 0; j < 2; j++) {
                    float v = c[mt][nt][half * 2 + j] * 0.125f;
                    c[mt][nt][half * 2 + j] = v;
                    m = fmaxf(m, v);
                }
            }
            m = fmaxf(m, __shfl_xor_sync(0xffffffffu, m, 1));
            m = fmaxf(m, __shfl_xor_sync(0xffffffffu, m, 2));
            const int row = mt * 16 + gid + half * 8;
            if (tq == 0) red[row * 8 + wid] = m;
        }
    }
    __syncthreads();
    #pragma unroll
    for (int i = 0; i < 8; i++) {
        int t = tid + i * 256;
        int f = t >> 5, g = t & 31;
        cp16(sb + VH_OFF + (f * VSTR + g * 8) * 2, vth + ((long)bh * DH_ + f) * L_ + g * 8);
    }
    #pragma unroll
    for (int i = 0; i < 8; i++) {
        int t = tid + i * 256;
        int f = t >> 5, g = t & 31;
        cp16(sb + VL_OFF + (f * VSTR + g * 8) * 2, vtl + ((long)bh * DH_ + f) * L_ + g * 8);
    }
    CP_COMMIT();

    if (tid < 64) {
        float m = red[tid * 8];
        #pragma unroll
        for (int w = 1; w < 8; w++) m = fmaxf(m, red[tid * 8 + w]);
        fin[tid] = m;
    }
    __syncthreads();

    #pragma unroll
    for (int mt = 0; mt < 4; mt++) {
        #pragma unroll
        for (int half = 0; half < 2; half++) {
            const int row = mt * 16 + gid + half * 8;
            const float M = fin[row];
            float s = 0.f;
            #pragma unroll
            for (int nt = 0; nt < 8; nt++) {
                #pragma unroll
                for (int j = 0; j < 2; j++) {
                    float e = __expf(c[mt][nt][half * 2 + j] - M);
                    c[mt][nt][half * 2 + j] = e;
                    s += e;
                }
            }
            s += __shfl_xor_sync(0xffffffffu, s, 1);
            s += __shfl_xor_sync(0xffffffffu, s, 2);
            if (tq == 0) red[row * 8 + wid] = s;
        }
    }
    __syncthreads();
    if (tid < 64) {
        float s = 0.f;
        #pragma unroll
        for (int w = 0; w < 8; w++) s += red[tid * 8 + w];
        fin[tid] = 1.f / s;
    }
    __syncthreads();

    #pragma unroll
    for (int mt = 0; mt < 4; mt++) {
        #pragma unroll
        for (int half = 0; half < 2; half++) {
            const int row = mt * 16 + gid + half * 8;
            const float inv = fin[row];
            #pragma unroll
            for (int nt = 0; nt < 8; nt++) {
                const int col = wid * 64 + nt * 8 + tq * 2;
                uint32_t hi, lo;
                split2(c[mt][nt][half * 2 + 0] * inv, c[mt][nt][half * 2 + 1] * inv, hi, lo);
                *(uint32_t*)(smc + PH_OFF + (row * PSTR + col) * 2) = hi;
                *(uint32_t*)(smc + PL_OFF + (row * PSTR + col) * 2) = lo;
            }
        }
    }
    CP_WAIT(0);
    __syncthreads();

    const int wm2 = wid >> 1, wn2 = wid & 1;
    const uint32_t a2_off = (uint32_t)(((wm2 * 16 + (lane & 15)) * PSTR + (lane >> 4) * 8) * 2);
    const uint32_t b2_off = (uint32_t)(((wn2 * 32 + (lane & 7) + (lane >> 4) * 8) * VSTR
                                       + ((lane >> 3) & 1) * 8) * 2);

    float c2[4][4];
    #pragma unroll
    for (int nt = 0; nt < 4; nt++)
        #pragma unroll
        for (int i = 0; i < 4; i++) c2[nt][i] = 0.f;

    for (int ch = 0; ch < 2; ch++) {
        if (ch == 1) {
            __syncthreads();
            #pragma unroll
            for (int i = 0; i < 8; i++) {
                int t = tid + i * 256;
                int f = t >> 5, g = t & 31;
                cp16(sb + VH_OFF + (f * VSTR + g * 8) * 2,
                     vth + ((long)bh * DH_ + f) * L_ + 256 + g * 8);
            }
            #pragma unroll
            for (int i = 0; i < 8; i++) {
                int t = tid + i * 256;
                int f = t >> 5, g = t & 31;
                cp16(sb + VL_OFF + (f * VSTR + g * 8) * 2,
                     vtl + ((long)bh * DH_ + f) * L_ + 256 + g * 8);
            }
            CP_COMMIT();
            CP_WAIT(0);
            __syncthreads();
        }
        const uint32_t pko = (uint32_t)(ch * 256 * 2);
        #pragma unroll
        for (int kk = 0; kk < 16; kk++) {
            const uint32_t ko = kk * 32;
            uint32_t pH[4], pL[4];
            LDSM_X4(pH[0], pH[1], pH[2], pH[3], sb + PH_OFF + a2_off + pko + ko);
            LDSM_X4(pL[0], pL[1], pL[2], pL[3], sb + PL_OFF + a2_off + pko + ko);
            uint32_t Bh2[8], Bl2[8];
            #pragma unroll
            for (int p = 0; p < 2; p++) {
                LDSM_X4(Bh2[p*4+0], Bh2[p*4+1], Bh2[p*4+2], Bh2[p*4+3], sb + VH_OFF + b2_off + p * (16*VSTR*2) + ko);
                LDSM_X4(Bl2[p*4+0], Bl2[p*4+1], Bl2[p*4+2], Bl2[p*4+3], sb + VL_OFF + b2_off + p * (16*VSTR*2) + ko);
            }
            #pragma unroll
            for (int nt = 0; nt < 4; nt++) {
                const int bi = (nt >> 1) * 4 + (nt & 1) * 2;
                mma_bf16(c2[nt], pL, Bh2[bi], Bh2[bi+1]);
                mma_bf16(c2[nt], pH, Bl2[bi], Bl2[bi+1]);
                mma_bf16(c2[nt], pH, Bh2[bi], Bh2[bi+1]);
            }
        }
    }

    #pragma unroll
    for (int nt = 0; nt < 4; nt++) {
        #pragma unroll
        for (int half = 0; half < 2; half++) {
            const int row = q0 + wm2 * 16 + gid + half * 8;
            const int col = head * DH_ + wn2 * 32 + nt * 8 + tq * 2;
            uint32_t hi, lo;
            split2(c2[nt][half * 2 + 0], c2[nt][half * 2 + 1], hi, lo);
            const long o = ((long)b * L_ + row) * D_ + col;
            *(uint32_t*)&ctxh[o] = hi;
            *(uint32_t*)&ctxl[o] = lo;
        }
    }
}

// ---------------- sparse GCN aggregation (agg1: gelu -> splits) ----------------
__global__ __launch_bounds__(256, 4)
void gcn_agg(const float* __restrict__ xw, const float* __restrict__ dinv,
             const int* __restrict__ start, const int* __restrict__ esrc,
             const float* __restrict__ ew, const float* __restrict__ bias,
             __nv_bfloat16* __restrict__ oh, __nv_bfloat16* __restrict__ ol)
{
    const int b  = blockIdx.x >> 6;
    const int dg = blockIdx.x & 63;
    const int wid = threadIdx.x >> 5, lane = threadIdx.x & 31;
    const int d = dg * 8 + wid;

    const float* xb = xw + (long)b * L_ * D_;
    float acc[24];
    #pragma unroll
    for (int j = 0; j < 24; j++) acc[j] = 0.f;

    const int s0 = start[b * (L_ + 1) + d];
    const int s1 = start[b * (L_ + 1) + d + 1];
    const int*   es = esrc + (long)b * E_;
    const float* we = ew   + (long)b * E_;

    for (int i = s0; i < s1; i++) {
        const int   s = es[i];
        const float w = we[i];
        const float* xr = xb + (long)s * D_ + lane;
        #pragma unroll
        for (int j = 0; j < 24; j++) acc[j] = fmaf(w, xr[32 * j], acc[j]);
    }
    {
        const float di = dinv[b * L_ + d];
        const float w = di * di;
        const float* xr = xb + (long)d * D_ + lane;
        #pragma unroll
        for (int j = 0; j < 24; j++) acc[j] = fmaf(w, xr[32 * j], acc[j]);
    }

    const long rbase = ((long)b * L_ + d) * D_;
    #pragma unroll
    for (int j = 0; j < 24; j++) {
        const int f = lane + 32 * j;
        const float v = gelu_f(acc[j] + bias[f]);
        __nv_bfloat16 hb = __float2bfloat16_rn(v);
        oh[rbase + f] = hb;
        ol[rbase + f] = __float2bfloat16_rn(v - __bfloat162float(hb));
    }
}

// ---------------- agg2 + fused n2-LayerNorm: yh/yl = LN(gelu(agg + bias); gam, bet) ----
__global__ __launch_bounds__(256, 4)
void gcn_agg_ln(const float* __restrict__ xw, const float* __restrict__ dinv,
                const int* __restrict__ start, const int* __restrict__ esrc,
                const float* __restrict__ ew, const float* __restrict__ bias,
                const float* __restrict__ gam, const float* __restrict__ bet,
                __nv_bfloat16* __restrict__ oh, __nv_bfloat16* __restrict__ ol)
{
    const int b  = blockIdx.x >> 6;
    const int dg = blockIdx.x & 63;
    const int wid = threadIdx.x >> 5, lane = threadIdx.x & 31;
    const int d = dg * 8 + wid;

    const float* xb = xw + (long)b * L_ * D_;
    float acc[24];
    #pragma unroll
    for (int j = 0; j < 24; j++) acc[j] = 0.f;

    const int s0 = start[b * (L_ + 1) + d];
    const int s1 = start[b * (L_ + 1) + d + 1];
    const int*   es = esrc + (long)b * E_;
    const float* we = ew   + (long)b * E_;

    for (int i = s0; i < s1; i++) {
        const int   s = es[i];
        const float w = we[i];
        const float* xr = xb + (long)s * D_ + lane;
        #pragma unroll
        for (int j = 0; j < 24; j++) acc[j] = fmaf(w, xr[32 * j], acc[j]);
    }
    {
        const float di = dinv[b * L_ + d];
        const float w = di * di;
        const float* xr = xb + (long)d * D_ + lane;
        #pragma unroll
        for (int j = 0; j < 24; j++) acc[j] = fmaf(w, xr[32 * j], acc[j]);
    }

    // gelu
    #pragma unroll
    for (int j = 0; j < 24; j++)
        acc[j] = gelu_f(acc[j] + bias[lane + 32 * j]);

    // warp LayerNorm over 768 features
    float s = 0.f;
    #pragma unroll
    for (int j = 0; j < 24; j++) s += acc[j];
    #pragma unroll
    for (int o = 16; o > 0; o >>= 1) s += __shfl_xor_sync(0xffffffffu, s, o);
    const float mean = s * (1.f / 768.f);

    float q = 0.f;
    #pragma unroll
    for (int j = 0; j < 24; j++) {
        acc[j] -= mean;
        q += acc[j] * acc[j];
    }
    #pragma unroll
    for (int o = 16; o > 0; o >>= 1) q += __shfl_xor_sync(0xffffffffu, q, o);
    const float r = rsqrtf(q * (1.f / 768.f) + 1e-12f);

    const long rbase = ((long)b * L_ + d) * D_;
    #pragma unroll
    for (int j = 0; j < 24; j++) {
        const int f = lane + 32 * j;
        const float v = acc[j] * r * gam[f] + bet[f];
        __nv_bfloat16 hb = __float2bfloat16_rn(v);
        oh[rbase + f] = hb;
        ol[rbase + f] = __float2bfloat16_rn(v - __bfloat162float(hb));
    }
}

// ---------------- CSR build ----------------
__global__ void csr_count(const int* __restrict__ edges, int* __restrict__ cnt)
{
    const int i = blockIdx.x * 256 + threadIdx.x;
    const int b = i / E_, e = i % E_;
    const int d = edges[(long)b * 2 * E_ + E_ + e];
    atomicAdd(&cnt[b * L_ + d], 1);
}

__global__ void csr_scan(const int* __restrict__ cnt, int* __restrict__ start)
{
    __shared__ int s[L_];
    const int b = blockIdx.x, t = threadIdx.x;
    s[t] = cnt[b * L_ + t];
    for (int off = 1; off < L_; off <<= 1) {
        __syncthreads();
        int v = (t >= off) ? s[t - off] : 0;
        __syncthreads();
        s[t] += v;
    }
    __syncthreads();
    start[b * (L_ + 1) + t + 1] = s[t];
    if (t == 0) start[b * (L_ + 1)] = 0;
}

__global__ void csr_fill(const int* __restrict__ edges, const float* __restrict__ dinv,
                         const int* __restrict__ start, int* __restrict__ cur,
                         int* __restrict__ esrc, float* __restrict__ ew)
{
    const int i = blockIdx.x * 256 + threadIdx.x;
    const int b = i / E_, e = i % E_;
    const int s = edges[(long)b * 2 * E_ + e];
    const int d = edges[(long)b * 2 * E_ + E_ + e];
    const int pos = start[b * (L_ + 1) + d] + atomicAdd(&cur[b * L_ + d], 1);
    esrc[(long)b * E_ + pos] = s;
    ew  [(long)b * E_ + pos] = dinv[b * L_ + s] * dinv[b * L_ + d];
}

// ---------------- split transpose (weights prep) ----------------
__global__ void transpose_split(const float* __restrict__ in,
                                __nv_bfloat16* __restrict__ outh,
                                __nv_bfloat16* __restrict__ outl,
                                int R, int C)
{
    __shared__ float t[32][33];
    const long z = blockIdx.z;
    in   += z * (long)R * C;
    outh += z * (long)R * C;
    outl += z * (long)R * C;
    const int c0 = blockIdx.x * 32, r0 = blockIdx.y * 32;
    const int tx = threadIdx.x, ty = threadIdx.y;
    #pragma unroll
    for (int i = 0; i < 32; i += 8)
        t[ty + i][tx] = in[(long)(r0 + ty + i) * C + c0 + tx];
    __syncthreads();
    #pragma unroll
    for (int i = 0; i < 32; i += 8) {
        float v = t[tx][ty + i];
        __nv_bfloat16 hb = __float2bfloat16_rn(v);
        float lo = v - __bfloat162float(hb);
        const long o = (long)(c0 + ty + i) * R + r0 + tx;
        outh[o] = hb;
        outl[o] = __float2bfloat16_rn(lo);
    }
}

// ---------------- split copy ----------------
__global__ void split_copy(const float* __restrict__ in,
                           __nv_bfloat16* __restrict__ oh, __nv_bfloat16* __restrict__ ol,
                           int n4)
{
    const int i = blockIdx.x * 256 + threadIdx.x;
    if (i >= n4) return;
    float4 v = ((const float4*)in)[i];
    uint32_t h0, l0, h1, l1;
    split2(v.x, v.y, h0, l0);
    split2(v.z, v.w, h1, l1);
    ((uint2*)oh)[i] = make_uint2(h0, h1);
    ((uint2*)ol)[i] = make_uint2(l0, l1);
}

// ---------------- bias-pair gather ----------------
__global__ void bias2_gather(const float* __restrict__ m3b, const float* __restrict__ m1b,
                             float* __restrict__ out)
{
    const int i = blockIdx.x * 256 + threadIdx.x;
    if (i >= NL_ * 2 * D_) return;
    const int l = i / (2 * D_), j = i % (2 * D_);
    out[i] = (j < D_) ? m3b[l * D_ + j] : m1b[l * D_ + j - D_];
}

// ---------------- LayerNorm ----------------
__global__ void ln_kernel(const float* __restrict__ in,
                          const float* __restrict__ gam,
                          const float* __restrict__ bet,
                          float* __restrict__ out,
                          __nv_bfloat16* __restrict__ outh,
                          __nv_bfloat16* __restrict__ outl)
{
    __shared__ float red[8];
    const int row = blockIdx.x;
    const int t = threadIdx.x;
    const int lane = t & 31, w = t >> 5;
    const float* xp = in + (long)row * D_;

    float v0 = xp[t], v1 = xp[t + 256], v2 = xp[t + 512];
    float s = v0 + v1 + v2;
    #pragma unroll
    for (int o = 16; o > 0; o >>= 1) s += __shfl_xor_sync(0xffffffffu, s, o);
    if (lane == 0) red[w] = s;
    __syncthreads();
    s = 0.f;
    #pragma unroll
    for (int i = 0; i < 8; i++) s += red[i];
    const float mean = s * (1.f / 768.f);
    __syncthreads();

    float d0 = v0 - mean, d1 = v1 - mean, d2 = v2 - mean;
    float q = d0 * d0 + d1 * d1 + d2 * d2;
    #pragma unroll
    for (int o = 16; o > 0; o >>= 1) q += __shfl_xor_sync(0xffffffffu, q, o);
    if (lane == 0) red[w] = q;
    __syncthreads();
    q = 0.f;
    #pragma unroll
    for (int i = 0; i < 8; i++) q += red[i];
    const float r = rsqrtf(q * (1.f / 768.f) + 1e-12f);

    const float o0 = d0 * r * gam[t]       + bet[t];
    const float o1 = d1 * r * gam[t + 256] + bet[t + 256];
    const float o2 = d2 * r * gam[t + 512] + bet[t + 512];
    if (out) {
        float* op = out + (long)row * D_;
        op[t] = o0; op[t + 256] = o1; op[t + 512] = o2;
    }
    if (outh) {
        __nv_bfloat16* oph = outh + (long)row * D_;
        __nv_bfloat16* opl = outl + (long)row * D_;
        __nv_bfloat16 h0 = __float2bfloat16_rn(o0);
        __nv_bfloat16 h1 = __float2bfloat16_rn(o1);
        __nv_bfloat16 h2 = __float2bfloat16_rn(o2);
        oph[t] = h0;       opl[t]       = __float2bfloat16_rn(o0 - __bfloat162float(h0));
        oph[t + 256] = h1; opl[t + 256] = __float2bfloat16_rn(o1 - __bfloat162float(h1));
        oph[t + 512] = h2; opl[t + 512] = __float2bfloat16_rn(o2 - __bfloat162float(h2));
    }
}

// ---------------- fused dual LayerNorm ----------------
__global__ void ln_dual_kernel(const float* __restrict__ in,
                               const float* __restrict__ g1, const float* __restrict__ b1,
                               const float* __restrict__ g2, const float* __restrict__ b2,
                               float* __restrict__ h1out,
                               __nv_bfloat16* __restrict__ s0h, __nv_bfloat16* __restrict__ s0l,
                               __nv_bfloat16* __restrict__ s1h, __nv_bfloat16* __restrict__ s1l)
{
    __shared__ float red[8];
    const int row = blockIdx.x;
    const int t = threadIdx.x;
    const int lane = t & 31, w = t >> 5;
    const float* xp = in + (long)row * D_;

    float v0 = xp[t], v1 = xp[t + 256], v2 = xp[t + 512];
    float s = v0 + v1 + v2;
    #pragma unroll
    for (int o = 16; o > 0; o >>= 1) s += __shfl_xor_sync(0xffffffffu, s, o);
    if (lane == 0) red[w] = s;
    __syncthreads();
    s = 0.f;
    #pragma unroll
    for (int i = 0; i < 8; i++) s += red[i];
    const float mean = s * (1.f / 768.f);
    __syncthreads();

    float d0 = v0 - mean, d1 = v1 - mean, d2 = v2 - mean;
    float q = d0 * d0 + d1 * d1 + d2 * d2;
    #pragma unroll
    for (int o = 16; o > 0; o >>= 1) q += __shfl_xor_sync(0xffffffffu, q, o);
    if (lane == 0) red[w] = q;
    __syncthreads();
    q = 0.f;
    #pragma unroll
    for (int i = 0; i < 8; i++) q += red[i];
    const float r = rsqrtf(q * (1.f / 768.f) + 1e-12f);

    const float o0 = d0 * r * g1[t]       + b1[t];
    const float o1 = d1 * r * g1[t + 256] + b1[t + 256];
    const float o2 = d2 * r * g1[t + 512] + b1[t + 512];
    {
        float* op = h1out + (long)row * D_;
        op[t] = o0; op[t + 256] = o1; op[t + 512] = o2;
        __nv_bfloat16* oph = s0h + (long)row * D_;
        __nv_bfloat16* opl = s0l + (long)row * D_;
        __nv_bfloat16 h0 = __float2bfloat16_rn(o0);
        __nv_bfloat16 h1 = __float2bfloat16_rn(o1);
        __nv_bfloat16 h2 = __float2bfloat16_rn(o2);
        oph[t] = h0;       opl[t]       = __float2bfloat16_rn(o0 - __bfloat162float(h0));
        oph[t + 256] = h1; opl[t + 256] = __float2bfloat16_rn(o1 - __bfloat162float(h1));
        oph[t + 512] = h2; opl[t + 512] = __float2bfloat16_rn(o2 - __bfloat162float(h2));
    }

    __syncthreads();
    float s2 = o0 + o1 + o2;
    #pragma unroll
    for (int o = 16; o > 0; o >>= 1) s2 += __shfl_xor_sync(0xffffffffu, s2, o);
    if (lane == 0) red[w] = s2;
    __syncthreads();
    s2 = 0.f;
    #pragma unroll
    for (int i = 0; i < 8; i++) s2 += red[i];
    const float mean2 = s2 * (1.f / 768.f);
    __syncthreads();

    float e0 = o0 - mean2, e1 = o1 - mean2, e2 = o2 - mean2;
    float q2 = e0 * e0 + e1 * e1 + e2 * e2;
    #pragma unroll
    for (int o = 16; o > 0; o >>= 1) q2 += __shfl_xor_sync(0xffffffffu, q2, o);
    if (lane == 0) red[w] = q2;
    __syncthreads();
    q2 = 0.f;
    #pragma unroll
    for (int i = 0; i < 8; i++) q2 += red[i];
    const float r2 = rsqrtf(q2 * (1.f / 768.f) + 1e-12f);

    const float p0 = e0 * r2 * g2[t]       + b2[t];
    const float p1 = e1 * r2 * g2[t + 256] + b2[t + 256];
    const float p2 = e2 * r2 * g2[t + 512] + b2[t + 512];
    {
        __nv_bfloat16* oph = s1h + (long)row * D_;
        __nv_bfloat16* opl = s1l + (long)row * D_;
        __nv_bfloat16 h0 = __float2bfloat16_rn(p0);
        __nv_bfloat16 h1 = __float2bfloat16_rn(p1);
        __nv_bfloat16 h2 = __float2bfloat16_rn(p2);
        oph[t] = h0;       opl[t]       = __float2bfloat16_rn(p0 - __bfloat162float(h0));
        oph[t + 256] = h1; opl[t + 256] = __float2bfloat16_rn(p1 - __bfloat162float(h1));
        oph[t + 512] = h2; opl[t + 512] = __float2bfloat16_rn(p2 - __bfloat162float(h2));
    }
}

// ---------------- degree ----------------
__global__ void deg_kernel(const int* __restrict__ edges, float* __restrict__ dinv)
{
    __shared__ float sdeg[L_];
    const int b = blockIdx.x, t = threadIdx.x;
    sdeg[t] = 1.f;
    __syncthreads();
    const int* dst = edges + (long)b * 2 * E_ + E_;
    for (int e = t; e < E_; e += L_) atomicAdd(&sdeg[dst[e]], 1.f);
    __syncthreads();
    dinv[b * L_ + t] = rsqrtf(sdeg[t]);
}

// ---------------- host side ----------------
static void launch_mma(int epi, int tn,
                       const __nv_bfloat16* Ah, const __nv_bfloat16* Al,
                       const __nv_bfloat16* Bh, const __nv_bfloat16* Bl,
                       const float* bias, const float* add,
                       float* C, __nv_bfloat16* Ch, __nv_bfloat16* Cl,
                       int Mr, int N, int K, int batch,
                       long sA, long sB, long sC, long sBias = 0,
                       __nv_bfloat16* Vh = 0, __nv_bfloat16* Vl = 0)
{
    dim3 grid(N / tn, Mr / TM_T, batch), block(256);
    if (tn == 256) {
        switch (epi) {
            case 0: mma_gemm<0,256><<<grid, block, SMEM_MMA(256)>>>(Ah, Al, Bh, Bl, bias, add, C, Ch, Cl, Vh, Vl, K, N, sA, sB, sC, sBias); break;
            case 1: mma_gemm<1,256><<<grid, block, SMEM_MMA(256)>>>(Ah, Al, Bh, Bl, bias, add, C, Ch, Cl, Vh, Vl, K, N, sA, sB, sC, sBias); break;
            case 2: mma_gemm<2,256><<<grid, block, SMEM_MMA(256)>>>(Ah, Al, Bh, Bl, bias, add, C, Ch, Cl, Vh, Vl, K, N, sA, sB, sC, sBias); break;
            case 3: mma_gemm<3,256><<<grid, block, SMEM_MMA(256)>>>(Ah, Al, Bh, Bl, bias, add, C, Ch, Cl, Vh, Vl, K, N, sA, sB, sC, sBias); break;
        }
    } else {
        switch (epi) {
            case 0: mma_gemm<0,192><<<grid, block, SMEM_MMA(192)>>>(Ah, Al, Bh, Bl, bias, add, C, Ch, Cl, Vh, Vl, K, N, sA, sB, sC, sBias); break;
            case 1: mma_gemm<1,192><<<grid, block, SMEM_MMA(192)>>>(Ah, Al, Bh, Bl, bias, add, C, Ch, Cl, Vh, Vl, K, N, sA, sB, sC, sBias); break;
            case 2: mma_gemm<2,192><<<grid, block, SMEM_MMA(192)>>>(Ah, Al, Bh, Bl, bias, add, C, Ch, Cl, Vh, Vl, K, N, sA, sB, sC, sBias); break;
            case 3: mma_gemm<3,192><<<grid, block, SMEM_MMA(192)>>>(Ah, Al, Bh, Bl, bias, add, C, Ch, Cl, Vh, Vl, K, N, sA, sB, sC, sBias); break;
        }
    }
}

extern "C" void kernel_launch(void* const* d_in, const int* in_sizes, int n_in,
                              void* d_out, int out_size)
{
    const float* hidden = (const float*)d_in[0];
    const int*   edges  = (const int*)  d_in[1];
    const float* Wqkv   = (const float*)d_in[2];
    const float* bqkv   = (const float*)d_in[3];
    const float* Wo     = (const float*)d_in[4];
    const float* bo     = (const float*)d_in[5];
    const float* ln1_s  = (const float*)d_in[6];
    const float* ln1_b  = (const float*)d_in[7];
    const float* n1_s   = (const float*)d_in[8];
    const float* n1_b   = (const float*)d_in[9];
    const float* m1_W   = (const float*)d_in[10];
    const float* m1_b   = (const float*)d_in[11];
    const float* c1_W   = (const float*)d_in[12];
    const float* c1_b   = (const float*)d_in[13];
    const float* c2_W   = (const float*)d_in[14];
    const float* c2_b   = (const float*)d_in[15];
    const float* n2_s   = (const float*)d_in[16];
    const float* n2_b   = (const float*)d_in[17];
    const float* m2_W   = (const float*)d_in[18];
    const float* m2_b   = (const float*)d_in[19];
    const float* m3_W   = (const float*)d_in[20];
    const float* m3_b   = (const float*)d_in[21];
    const float* int_W  = (const float*)d_in[22];
    const float* int_b  = (const float*)d_in[23];
    const float* out_W  = (const float*)d_in[24];
    const float* out_b  = (const float*)d_in[25];
    const float* ln2_s  = (const float*)d_in[26];
    const float* ln2_b  = (const float*)d_in[27];

    float *h, *h1, *y, *gg, *dinv, *pairC, *bias2, *ew;
    int *cnt, *startp, *cur, *esrc;
    __nv_bfloat16 *hh, *hl, *qkvh, *qkvl, *vth, *vtl, *ctxh, *ctxl,
                  *pairAh, *pairAl, *pairCh, *pairCl,
                  *xh, *xl, *yh, *yl, *ggh, *ggl, *midh, *midl, *wTh, *wTl;
    cudaGetSymbolAddress((void**)&h,    g_h);
    cudaGetSymbolAddress((void**)&h1,   g_h1);
    cudaGetSymbolAddress((void**)&y,    g_y);
    cudaGetSymbolAddress((void**)&gg,   g_g);
    cudaGetSymbolAddress((void**)&dinv, g_dinv);
    cudaGetSymbolAddress((void**)&pairC, g_pairC);
    cudaGetSymbolAddress((void**)&bias2, g_bias2);
    cudaGetSymbolAddress((void**)&cnt,   g_cnt);
    cudaGetSymbolAddress((void**)&startp, g_start);
    cudaGetSymbolAddress((void**)&cur,   g_cur);
    cudaGetSymbolAddress((void**)&esrc,  g_esrc);
    cudaGetSymbolAddress((void**)&ew,    g_ew);
    cudaGetSymbolAddress((void**)&hh,   g_hh);   cudaGetSymbolAddress((void**)&hl,   g_hl);
    cudaGetSymbolAddress((void**)&qkvh, g_qkvh); cudaGetSymbolAddress((void**)&qkvl, g_qkvl);
    cudaGetSymbolAddress((void**)&vth,  g_vth);  cudaGetSymbolAddress((void**)&vtl,  g_vtl);
    cudaGetSymbolAddress((void**)&ctxh, g_ctxh); cudaGetSymbolAddress((void**)&ctxl, g_ctxl);
    cudaGetSymbolAddress((void**)&pairAh, g_pairAh); cudaGetSymbolAddress((void**)&pairAl, g_pairAl);
    cudaGetSymbolAddress((void**)&pairCh, g_pairCh); cudaGetSymbolAddress((void**)&pairCl, g_pairCl);
    cudaGetSymbolAddress((void**)&xh,   g_xh);   cudaGetSymbolAddress((void**)&xl,   g_xl);
    cudaGetSymbolAddress((void**)&yh,   g_yh);   cudaGetSymbolAddress((void**)&yl,   g_yl);
    cudaGetSymbolAddress((void**)&ggh,  g_ggh);  cudaGetSymbolAddress((void**)&ggl,  g_ggl);
    cudaGetSymbolAddress((void**)&midh, g_midh); cudaGetSymbolAddress((void**)&midl, g_midl);
    cudaGetSymbolAddress((void**)&wTh,  g_wTh);  cudaGetSymbolAddress((void**)&wTl,  g_wTl);

    cudaFuncSetAttribute(mma_gemm<0,256>, cudaFuncAttributeMaxDynamicSharedMemorySize, SMEM_MMA(256));
    cudaFuncSetAttribute(mma_gemm<1,256>, cudaFuncAttributeMaxDynamicSharedMemorySize, SMEM_MMA(256));
    cudaFuncSetAttribute(mma_gemm<2,256>, cudaFuncAttributeMaxDynamicSharedMemorySize, SMEM_MMA(256));
    cudaFuncSetAttribute(mma_gemm<3,256>, cudaFuncAttributeMaxDynamicSharedMemorySize, SMEM_MMA(256));
    cudaFuncSetAttribute(mma_gemm<0,192>, cudaFuncAttributeMaxDynamicSharedMemorySize, SMEM_MMA(192));
    cudaFuncSetAttribute(mma_gemm<1,192>, cudaFuncAttributeMaxDynamicSharedMemorySize, SMEM_MMA(192));
    cudaFuncSetAttribute(mma_gemm<2,192>, cudaFuncAttributeMaxDynamicSharedMemorySize, SMEM_MMA(192));
    cudaFuncSetAttribute(mma_gemm<3,192>, cudaFuncAttributeMaxDynamicSharedMemorySize, SMEM_MMA(192));
    cudaFuncSetAttribute(attn_fused, cudaFuncAttributeMaxDynamicSharedMemorySize, SMEM_ATT);

    // setup: hidden copy + split, graph structure (CSR), bias pairs
    cudaMemcpyAsync(h, hidden, sizeof(float) * M_ * D_, cudaMemcpyDeviceToDevice);
    split_copy<<<(M_ * D_ / 4 + 255) / 256, 256>>>(hidden, hh, hl, M_ * D_ / 4);
    deg_kernel<<<B_, L_>>>(edges, dinv);
    cudaMemsetAsync(cnt, 0, sizeof(int) * B_ * L_);
    cudaMemsetAsync(cur, 0, sizeof(int) * B_ * L_);
    csr_count<<<(B_ * E_) / 256, 256>>>(edges, cnt);
    csr_scan<<<B_, L_>>>(cnt, startp);
    csr_fill<<<(B_ * E_) / 256, 256>>>(edges, dinv, startp, cur, esrc, ew);
    bias2_gather<<<(NL_ * 2 * D_ + 255) / 256, 256>>>(m3_b, m1_b, bias2);

    dim3 tb(32, 8);
    transpose_split<<<dim3(TD_/32, D_/32, NL_), tb>>>(Wqkv, wTh + OFF_QKV, wTl + OFF_QKV, D_, TD_);
    transpose_split<<<dim3(D_/32,  D_/32, NL_), tb>>>(Wo,   wTh + OFF_WO,  wTl + OFF_WO,  D_, D_);
    transpose_split<<<dim3(D_/32,  D_/32, NL_), tb>>>(m1_W, wTh + OFF_M1,  wTl + OFF_M1,  D_, D_);
    transpose_split<<<dim3(D_/32,  D_/32, NL_), tb>>>(c1_W, wTh + OFF_C1,  wTl + OFF_C1,  D_, D_);
    transpose_split<<<dim3(D_/32,  D_/32, NL_), tb>>>(c2_W, wTh + OFF_C2,  wTl + OFF_C2,  D_, D_);
    transpose_split<<<dim3(D_/32,  D_/32, NL_), tb>>>(m2_W, wTh + OFF_M2,  wTl + OFF_M2,  D_, D_);
    transpose_split<<<dim3(D_/32,  D_/32, NL_), tb>>>(m3_W, wTh + OFF_M3,  wTl + OFF_M3,  D_, D_);
    transpose_split<<<dim3(DF_/32, D_/32, NL_), tb>>>(int_W, wTh + OFF_INT, wTl + OFF_INT, D_, DF_);
    transpose_split<<<dim3(D_/32,  DF_/32, NL_), tb>>>(out_W, wTh + OFF_OUT, wTl + OFF_OUT, DF_, D_);

    const long MD = (long)M_ * D_;

    for (int l = 0; l < NL_; l++) {
        const long oQ = OFF_QKV + (long)l * TD_ * D_;
        const long oW = OFF_WO  + (long)l * D_ * D_;
        const long oc1 = OFF_C1 + (long)l * D_ * D_;
        const long oc2 = OFF_C2 + (long)l * D_ * D_;
        const long o2 = OFF_M2  + (long)l * D_ * D_;
        const long o3 = OFF_M3  + (long)l * D_ * D_;
        const long oi = OFF_INT + (long)l * DF_ * D_;
        const long oo = OFF_OUT + (long)l * D_ * DF_;

        const float* bqkv_l = bqkv + (long)l * TD_;
        const float* bo_l   = bo   + (long)l * D_;
        const float* ln1s = ln1_s + (long)l * D_;
        const float* ln1b = ln1_b + (long)l * D_;
        const float* n1s  = n1_s + (long)l * D_;
        const float* n1b  = n1_b + (long)l * D_;
        const float* c1b  = c1_b + (long)l * D_;
        const float* c2b  = c2_b + (long)l * D_;
        const float* n2s  = n2_s + (long)l * D_;
        const float* n2b  = n2_b + (long)l * D_;
        const float* m2b  = m2_b + (long)l * D_;
        const float* intb = int_b + (long)l * DF_;
        const float* outb = out_b + (long)l * D_;
        const float* ln2s = ln2_s + (long)l * D_;
        const float* ln2b = ln2_b + (long)l * D_;

        // qkv = h @ Wqkv + b  (V third written transposed into vth/vtl by epilogue)
        launch_mma(0, 256, hh, hl, wTh + oQ, wTl + oQ, bqkv_l, 0, 0, qkvh, qkvl,
                   M_, TD_, D_, 1, 0, 0, 0, 0, vth, vtl);
        // attention (fused scores+softmax+ctx; P stays in smem)
        attn_fused<<<dim3(BH_, L_ / 64), 256, SMEM_ATT>>>(qkvh, qkvl, vth, vtl, ctxh, ctxl);
        // h1 = LN(ctx @ Wo + bo + h); fused second LN(n1)
        launch_mma(1, 192, ctxh, ctxl, wTh + oW, wTl + oW, bo_l, h, y, 0, 0, M_, D_, D_, 1, 0, 0, 0);
        ln_dual_kernel<<<M_, 256>>>(y, ln1s, ln1b, n1s, n1b, h1,
                                    pairAh, pairAl, pairAh + MD, pairAl + MD);
        // batched pair: z0 res = gelu(h1@m3+b3); z1 x = gelu(LN@m1+b1)
        launch_mma(2, 192, pairAh, pairAl, wTh + o3, wTl + o3, bias2 + (long)l * 2 * D_, 0,
                   pairC, pairCh, pairCl, M_, D_, D_, 2, MD, OFF_M1 - OFF_M3, MD, D_);
        // GCN 1: y = x @ c1W (fp32); x = gelu(gather(y) + c1b) -> splits
        launch_mma(0, 192, pairCh + MD, pairCl + MD, wTh + oc1, wTl + oc1, 0, 0, y, 0, 0, M_, D_, D_, 1, 0, 0, 0);
        gcn_agg<<<B_ * 64, 256>>>(y, dinv, startp, esrc, ew, c1b, xh, xl);
        // GCN 2: y = x @ c2W (fp32); yh/yl = LN(gelu(gather(y) + c2b); n2)   [fused]
        launch_mma(0, 192, xh, xl, wTh + oc2, wTl + oc2, 0, 0, y, 0, 0, M_, D_, D_, 1, 0, 0, 0);
        gcn_agg_ln<<<B_ * 64, 256>>>(y, dinv, startp, esrc, ew, c2b, n2s, n2b, yh, yl);
        // g = res + gelu(LN @ m2 + b)
        launch_mma(3, 192, yh, yl, wTh + o2, wTl + o2, m2b, pairC, gg, ggh, ggl, M_, D_, D_, 1, 0, 0, 0);
        // FFN
        launch_mma(2, 256, ggh, ggl, wTh + oi, wTl + oi, intb, 0, 0, midh, midl, M_, DF_, D_, 1, 0, 0, 0);
        launch_mma(1, 192, midh, midl, wTh + oo, wTl + oo, outb, gg, y, 0, 0, M_, D_, DF_, 1, 0, 0, 0);
        if (l == NL_ - 1)
            ln_kernel<<<M_, 256>>>(y, ln2s, ln2b, (float*)d_out, 0, 0);
        else
            ln_kernel<<<M_, 256>>>(y, ln2s, ln2b, h, hh, hl);
    }
}

// round 16
// speedup vs baseline: 1.0518x; 1.0518x over previous
#include <cuda_runtime.h>
#include <cuda_bf16.h>
#include <math.h>
#include <stdint.h>

// ---------------- problem constants ----------------
#define B_   8
#define L_   512
#define D_   768
#define NL_  12
#define E_   8192
#define H_   12
#define DH_  64
#define DF_  3072
#define M_   4096       // B_*L_
#define TD_  2304       // 3*D_
#define BH_  96         // B_*H_

// ---------------- mma-gemm tile config ----------------
#define TM_T 128
#define TK_T 64
#define GRST 72                        // smem row stride (bf16), 64 elems + 8 pad
#define A_TILE_B (TM_T * GRST * 2)     // 18432 bytes per array per stage
#define SMEM_MMA(TNT) (4 * A_TILE_B + 4 * (TNT) * GRST * 2)

// ---------------- fused attention smem layout (bytes) ----------------
#define KRST 72
#define PSTR 520     // P row stride (bf16)
#define VSTR 264     // V chunk row stride (bf16)
#define PH_OFF  0
#define PL_OFF  66560
#define VH_OFF  133120
#define VL_OFF  166912
#define QH_OFF  200704
#define QL_OFF  209920
#define RED_OFF 219136
#define FIN_OFF 221184
#define SMEM_ATT 221440
#define KH_OFF  0
#define KL_OFF  73728

// ---------------- scratch (static device memory) ----------------
__device__ float g_h  [M_ * D_];
__device__ float g_h1 [M_ * D_];
__device__ float g_y  [M_ * D_];
__device__ float g_g  [M_ * D_];
__device__ float g_dinv[B_ * L_];
__device__ float g_pairC[2 * M_ * D_];
__device__ float g_bias2[NL_ * 2 * D_];
// CSR for sparse GCN aggregation
__device__ int   g_cnt [B_ * L_];
__device__ int   g_start[B_ * (L_ + 1)];
__device__ int   g_cur [B_ * L_];
__device__ int   g_esrc[B_ * E_];
__device__ float g_ew  [B_ * E_];
// bf16 hi/lo pairs
__device__ __nv_bfloat16 g_hh [M_ * D_],  g_hl [M_ * D_];
__device__ __nv_bfloat16 g_qkvh[M_ * TD_], g_qkvl[M_ * TD_];
__device__ __nv_bfloat16 g_vth[BH_ * DH_ * L_], g_vtl[BH_ * DH_ * L_];
__device__ __nv_bfloat16 g_ctxh[M_ * D_], g_ctxl[M_ * D_];
__device__ __nv_bfloat16 g_pairAh[2 * M_ * D_], g_pairAl[2 * M_ * D_];
__device__ __nv_bfloat16 g_pairCh[2 * M_ * D_], g_pairCl[2 * M_ * D_];
__device__ __nv_bfloat16 g_xh [M_ * D_],  g_xl [M_ * D_];
__device__ __nv_bfloat16 g_yh [M_ * D_],  g_yl [M_ * D_];
__device__ __nv_bfloat16 g_ggh[M_ * D_],  g_ggl[M_ * D_];
__device__ __nv_bfloat16 g_midh[M_ * DF_], g_midl[M_ * DF_];
__device__ __nv_bfloat16 g_wTh[120324096], g_wTl[120324096];

#define OFF_QKV 0L
#define OFF_WO  21233664L
#define OFF_M1  28311552L
#define OFF_C1  35389440L
#define OFF_C2  42467328L
#define OFF_M2  49545216L
#define OFF_M3  56623104L
#define OFF_INT 63700992L
#define OFF_OUT 92012544L

// ---------------- helpers ----------------
__device__ __forceinline__ uint32_t smem_u32(const void* p) {
    uint32_t a;
    asm("{ .reg .u64 t; cvta.to.shared.u64 t, %1; cvt.u32.u64 %0, t; }" : "=r"(a) : "l"(p));
    return a;
}
__device__ __forceinline__ float gelu_f(float v) {
    return 0.5f * v * (1.0f + erff(v * 0.7071067811865475f));
}
__device__ __forceinline__ void cp16(uint32_t dst, const void* src) {
    asm volatile("cp.async.cg.shared.global [%0], [%1], 16;" :: "r"(dst), "l"(src));
}
#define CP_COMMIT() asm volatile("cp.async.commit_group;" ::: "memory")
#define CP_WAIT(n)  asm volatile("cp.async.wait_group %0;" :: "n"(n) : "memory")

#define LDSM_X4(r0, r1, r2, r3, addr) \
    asm volatile("ldmatrix.sync.aligned.m8n8.x4.shared.b16 {%0,%1,%2,%3}, [%4];" \
        : "=r"(r0), "=r"(r1), "=r"(r2), "=r"(r3) : "r"(addr))

__device__ __forceinline__ void split2(float vx, float vy, uint32_t& hi, uint32_t& lo) {
    __nv_bfloat162 h = __floats2bfloat162_rn(vx, vy);
    float rx = vx - __bfloat162float(h.x);
    float ry = vy - __bfloat162float(h.y);
    __nv_bfloat162 l = __floats2bfloat162_rn(rx, ry);
    hi = *reinterpret_cast<uint32_t*>(&h);
    lo = *reinterpret_cast<uint32_t*>(&l);
}

__device__ __forceinline__ void mma_bf16(float c[4], const uint32_t a[4], uint32_t b0, uint32_t b1) {
    asm volatile(
        "mma.sync.aligned.m16n8k16.row.col.f32.bf16.bf16.f32 "
        "{%0,%1,%2,%3}, {%4,%5,%6,%7}, {%8,%9}, {%0,%1,%2,%3};"
        : "+f"(c[0]), "+f"(c[1]), "+f"(c[2]), "+f"(c[3])
        : "r"(a[0]), "r"(a[1]), "r"(a[2]), "r"(a[3]), "r"(b0), "r"(b1));
}

// ---------------- bf16x3 mma.sync GEMM (TK=64 chunks, templated tile N) ----------------
template <int EPI, int TNT>
__global__ __launch_bounds__(256, 1)
void mma_gemm(const __nv_bfloat16* __restrict__ Ah, const __nv_bfloat16* __restrict__ Al,
              const __nv_bfloat16* __restrict__ Bh, const __nv_bfloat16* __restrict__ Bl,
              const float* __restrict__ bias, const float* __restrict__ add,
              float* __restrict__ C, __nv_bfloat16* __restrict__ Ch, __nv_bfloat16* __restrict__ Cl,
              int K, int N, long sA, long sB, long sC, long sBias)
{
    constexpr int WNT = TNT / 4;
    constexpr int NTI = WNT / 8;
    constexpr int PB  = WNT / 16;
    constexpr int BCP = TNT / 32;
    constexpr int B_TILE_B = TNT * GRST * 2;

    extern __shared__ char smc[];
    const uint32_t sAh_u = smem_u32(smc);
    const uint32_t sAl_u = sAh_u + 2 * A_TILE_B;
    const uint32_t sBh_u = sAh_u + 4 * A_TILE_B;
    const uint32_t sBl_u = sBh_u + 2 * B_TILE_B;

    const int tid = threadIdx.x;
    const long z = blockIdx.z;
    Ah += z * sA; Al += z * sA;
    Bh += z * sB; Bl += z * sB;
    if (C)  C  += z * sC;
    if (Ch) { Ch += z * sC; Cl += z * sC; }
    const float* biasp = bias ? bias + z * sBias : (const float*)0;
    const float* addp = (EPI == 1 || EPI == 3) ? add + z * sC : (const float*)0;

    const int m0 = blockIdx.y * TM_T;
    const int n0 = blockIdx.x * TNT;
    const int wid = tid >> 5, lane = tid & 31;
    const int wm = wid >> 2, wn = wid & 3;
    const int gid = lane >> 2, tq = lane & 3;

    const uint32_t a_off = (uint32_t)(((wm * 64 + (lane & 15)) * GRST + (lane >> 4) * 8) * 2);
    const uint32_t b_off = (uint32_t)(((wn * WNT + (lane & 7) + (lane >> 4) * 8) * GRST
                                      + ((lane >> 3) & 1) * 8) * 2);

    float c[4][NTI][4];
    #pragma unroll
    for (int mt = 0; mt < 4; mt++)
        #pragma unroll
        for (int nt = 0; nt < NTI; nt++)
            #pragma unroll
            for (int i = 0; i < 4; i++) c[mt][nt][i] = 0.f;

    const int nck = K / TK_T;

    auto prefetch = [&](int s, int k0) {
        #pragma unroll
        for (int i = 0; i < 4; i++) {
            int t = tid + i * 256;
            int r = t >> 3, g = t & 7;
            cp16(sAh_u + s * A_TILE_B + (r * GRST + g * 8) * 2,
                 Ah + (long)(m0 + r) * K + k0 + g * 8);
        }
        #pragma unroll
        for (int i = 0; i < 4; i++) {
            int t = tid + i * 256;
            int r = t >> 3, g = t & 7;
            cp16(sAl_u + s * A_TILE_B + (r * GRST + g * 8) * 2,
                 Al + (long)(m0 + r) * K + k0 + g * 8);
        }
        #pragma unroll
        for (int i = 0; i < BCP; i++) {
            int t = tid + i * 256;
            int r = t >> 3, g = t & 7;
            cp16(sBh_u + s * B_TILE_B + (r * GRST + g * 8) * 2,
                 Bh + (long)(n0 + r) * K + k0 + g * 8);
        }
        #pragma unroll
        for (int i = 0; i < BCP; i++) {
            int t = tid + i * 256;
            int r = t >> 3, g = t & 7;
            cp16(sBl_u + s * B_TILE_B + (r * GRST + g * 8) * 2,
                 Bl + (long)(n0 + r) * K + k0 + g * 8);
        }
        CP_COMMIT();
    };

    prefetch(0, 0);

    for (int ck = 0; ck < nck; ck++) {
        if (ck + 1 < nck) { prefetch((ck + 1) & 1, (ck + 1) * TK_T); CP_WAIT(1); }
        else              { CP_WAIT(0); }
        __syncthreads();

        const int st = ck & 1;
        const uint32_t aH = sAh_u + st * A_TILE_B + a_off;
        const uint32_t aL = sAl_u + st * A_TILE_B + a_off;
        const uint32_t bH = sBh_u + st * B_TILE_B + b_off;
        const uint32_t bL = sBl_u + st * B_TILE_B + b_off;

        #pragma unroll
        for (int kk = 0; kk < 4; kk++) {
            const uint32_t ko = kk * 32;
            uint32_t Bhr[PB * 4], Blr[PB * 4];
            #pragma unroll
            for (int p = 0; p < PB; p++) {
                LDSM_X4(Bhr[p*4+0], Bhr[p*4+1], Bhr[p*4+2], Bhr[p*4+3], bH + p * (16*GRST*2) + ko);
                LDSM_X4(Blr[p*4+0], Blr[p*4+1], Blr[p*4+2], Blr[p*4+3], bL + p * (16*GRST*2) + ko);
            }
            #pragma unroll
            for (int mt = 0; mt < 4; mt++) {
                uint32_t ah[4], al[4];
                LDSM_X4(ah[0], ah[1], ah[2], ah[3], aH + mt * (16*GRST*2) + ko);
                LDSM_X4(al[0], al[1], al[2], al[3], aL + mt * (16*GRST*2) + ko);
                #pragma unroll
                for (int nt = 0; nt < NTI; nt++) {
                    const int bi = (nt >> 1) * 4 + (nt & 1) * 2;
                    mma_bf16(c[mt][nt], al, Bhr[bi], Bhr[bi+1]);
                }
                #pragma unroll
                for (int nt = 0; nt < NTI; nt++) {
                    const int bi = (nt >> 1) * 4 + (nt & 1) * 2;
                    mma_bf16(c[mt][nt], ah, Blr[bi], Blr[bi+1]);
                }
                #pragma unroll
                for (int nt = 0; nt < NTI; nt++) {
                    const int bi = (nt >> 1) * 4 + (nt & 1) * 2;
                    mma_bf16(c[mt][nt], ah, Bhr[bi], Bhr[bi+1]);
                }
            }
        }
        __syncthreads();
    }

    #pragma unroll
    for (int mt = 0; mt < 4; mt++) {
        const int r0 = m0 + wm * 64 + mt * 16 + gid;
        #pragma unroll
        for (int nt = 0; nt < NTI; nt++) {
            const int col = n0 + wn * WNT + nt * 8 + tq * 2;
            float bx = 0.f, by = 0.f;
            if (biasp) { bx = biasp[col]; by = biasp[col + 1]; }
            #pragma unroll
            for (int half = 0; half < 2; half++) {
                const int r = r0 + half * 8;
                float vx = c[mt][nt][half * 2 + 0] + bx;
                float vy = c[mt][nt][half * 2 + 1] + by;
                if (EPI == 2 || EPI == 3) { vx = gelu_f(vx); vy = gelu_f(vy); }
                if (EPI == 1 || EPI == 3) {
                    const float* ap = &addp[(long)r * N + col];
                    vx += ap[0]; vy += ap[1];
                }
                if (C) *(float2*)&C[(long)r * N + col] = make_float2(vx, vy);
                if (Ch) {
                    uint32_t hi, lo;
                    split2(vx, vy, hi, lo);
                    *(uint32_t*)&Ch[(long)r * N + col] = hi;
                    *(uint32_t*)&Cl[(long)r * N + col] = lo;
                }
            }
        }
    }
}

// ---------------- fused attention: S=softmax(QK^T/8) in regs -> P in smem -> ctx=P@V ----
__global__ __launch_bounds__(256, 1)
void attn_fused(const __nv_bfloat16* __restrict__ qkvh,
                const __nv_bfloat16* __restrict__ qkvl,
                const __nv_bfloat16* __restrict__ vth, const __nv_bfloat16* __restrict__ vtl,
                __nv_bfloat16* __restrict__ ctxh, __nv_bfloat16* __restrict__ ctxl)
{
    extern __shared__ char smc[];
    const uint32_t sb = smem_u32(smc);
    float* red = (float*)(smc + RED_OFF);
    float* fin = (float*)(smc + FIN_OFF);

    const int bh = blockIdx.x;
    const int b = bh / H_, head = bh % H_;
    const int q0 = blockIdx.y * 64;
    const int tid = threadIdx.x;
    const int wid = tid >> 5, lane = tid & 31;
    const int gid = lane >> 2, tq = lane & 3;

    const long qbase = (long)b * L_ * TD_ + head * DH_;

    #pragma unroll
    for (int i = 0; i < 16; i++) {
        int t = tid + i * 256;
        int r = t >> 3, g = t & 7;
        cp16(sb + KH_OFF + (r * KRST + g * 8) * 2, qkvh + qbase + (long)r * TD_ + D_ + g * 8);
    }
    #pragma unroll
    for (int i = 0; i < 16; i++) {
        int t = tid + i * 256;
        int r = t >> 3, g = t & 7;
        cp16(sb + KL_OFF + (r * KRST + g * 8) * 2, qkvl + qbase + (long)r * TD_ + D_ + g * 8);
    }
    #pragma unroll
    for (int i = 0; i < 2; i++) {
        int t = tid + i * 256;
        int r = t >> 3, g = t & 7;
        cp16(sb + QH_OFF + (r * KRST + g * 8) * 2, qkvh + qbase + (long)(q0 + r) * TD_ + g * 8);
    }
    #pragma unroll
    for (int i = 0; i < 2; i++) {
        int t = tid + i * 256;
        int r = t >> 3, g = t & 7;
        cp16(sb + QL_OFF + (r * KRST + g * 8) * 2, qkvl + qbase + (long)(q0 + r) * TD_ + g * 8);
    }
    CP_COMMIT();
    CP_WAIT(0);
    __syncthreads();

    const uint32_t a_off = (uint32_t)(((lane & 15) * KRST + (lane >> 4) * 8) * 2);
    const uint32_t b_off = (uint32_t)(((wid * 64 + (lane & 7) + (lane >> 4) * 8) * KRST
                                      + ((lane >> 3) & 1) * 8) * 2);

    float c[4][8][4];
    #pragma unroll
    for (int mt = 0; mt < 4; mt++)
        #pragma unroll
        for (int nt = 0; nt < 8; nt++)
            #pragma unroll
            for (int i = 0; i < 4; i++) c[mt][nt][i] = 0.f;

    #pragma unroll
    for (int kk = 0; kk < 4; kk++) {
        const uint32_t ko = kk * 32;
        uint32_t Bhr[16], Blr[16];
        #pragma unroll
        for (int p = 0; p < 4; p++) {
            LDSM_X4(Bhr[p*4+0], Bhr[p*4+1], Bhr[p*4+2], Bhr[p*4+3], sb + KH_OFF + b_off + p * (16*KRST*2) + ko);
            LDSM_X4(Blr[p*4+0], Blr[p*4+1], Blr[p*4+2], Blr[p*4+3], sb + KL_OFF + b_off + p * (16*KRST*2) + ko);
        }
        #pragma unroll
        for (int mt = 0; mt < 4; mt++) {
            uint32_t ah[4], al[4];
            LDSM_X4(ah[0], ah[1], ah[2], ah[3], sb + QH_OFF + a_off + mt * (16*KRST*2) + ko);
            LDSM_X4(al[0], al[1], al[2], al[3], sb + QL_OFF + a_off + mt * (16*KRST*2) + ko);
            #pragma unroll
            for (int nt = 0; nt < 8; nt++) {
                const int bi = (nt >> 1) * 4 + (nt & 1) * 2;
                mma_bf16(c[mt][nt], al, Bhr[bi], Bhr[bi+1]);
                mma_bf16(c[mt][nt], ah, Blr[bi], Blr[bi+1]);
                mma_bf16(c[mt][nt], ah, Bhr[bi], Bhr[bi+1]);
            }
        }
    }

    #pragma unroll
    for (int mt = 0; mt < 4; mt++) {
        #pragma unroll
        for (int half = 0; half < 2; half++) {
            float m = -3.0e38f;
            #pragma unroll
            for (int nt = 0; nt < 8; nt++) {
                #pragma unroll
                for (int j = 0; j < 2; j++) {
                    float v = c[mt][nt][half * 2 + j] * 0.125f;
                    c[mt][nt][half * 2 + j] = v;
                    m = fmaxf(m, v);
                }
            }
            m = fmaxf(m, __shfl_xor_sync(0xffffffffu, m, 1));
            m = fmaxf(m, __shfl_xor_sync(0xffffffffu, m, 2));
            const int row = mt * 16 + gid + half * 8;
            if (tq == 0) red[row * 8 + wid] = m;
        }
    }
    __syncthreads();
    #pragma unroll
    for (int i = 0; i < 8; i++) {
        int t = tid + i * 256;
        int f = t >> 5, g = t & 31;
        cp16(sb + VH_OFF + (f * VSTR + g * 8) * 2, vth + ((long)bh * DH_ + f) * L_ + g * 8);
    }
    #pragma unroll
    for (int i = 0; i < 8; i++) {
        int t = tid + i * 256;
        int f = t >> 5, g = t & 31;
        cp16(sb + VL_OFF + (f * VSTR + g * 8) * 2, vtl + ((long)bh * DH_ + f) * L_ + g * 8);
    }
    CP_COMMIT();

    if (tid < 64) {
        float m = red[tid * 8];
        #pragma unroll
        for (int w = 1; w < 8; w++) m = fmaxf(m, red[tid * 8 + w]);
        fin[tid] = m;
    }
    __syncthreads();

    #pragma unroll
    for (int mt = 0; mt < 4; mt++) {
        #pragma unroll
        for (int half = 0; half < 2; half++) {
            const int row = mt * 16 + gid + half * 8;
            const float M = fin[row];
            float s = 0.f;
            #pragma unroll
            for (int nt = 0; nt < 8; nt++) {
                #pragma unroll
                for (int j = 0; j < 2; j++) {
                    float e = __expf(c[mt][nt][half * 2 + j] - M);
                    c[mt][nt][half * 2 + j] = e;
                    s += e;
                }
            }
            s += __shfl_xor_sync(0xffffffffu, s, 1);
            s += __shfl_xor_sync(0xffffffffu, s, 2);
            if (tq == 0) red[row * 8 + wid] = s;
        }
    }
    __syncthreads();
    if (tid < 64) {
        float s = 0.f;
        #pragma unroll
        for (int w = 0; w < 8; w++) s += red[tid * 8 + w];
        fin[tid] = 1.f / s;
    }
    __syncthreads();

    #pragma unroll
    for (int mt = 0; mt < 4; mt++) {
        #pragma unroll
        for (int half = 0; half < 2; half++) {
            const int row = mt * 16 + gid + half * 8;
            const float inv = fin[row];
            #pragma unroll
            for (int nt = 0; nt < 8; nt++) {
                const int col = wid * 64 + nt * 8 + tq * 2;
                uint32_t hi, lo;
                split2(c[mt][nt][half * 2 + 0] * inv, c[mt][nt][half * 2 + 1] * inv, hi, lo);
                *(uint32_t*)(smc + PH_OFF + (row * PSTR + col) * 2) = hi;
                *(uint32_t*)(smc + PL_OFF + (row * PSTR + col) * 2) = lo;
            }
        }
    }
    CP_WAIT(0);
    __syncthreads();

    const int wm2 = wid >> 1, wn2 = wid & 1;
    const uint32_t a2_off = (uint32_t)(((wm2 * 16 + (lane & 15)) * PSTR + (lane >> 4) * 8) * 2);
    const uint32_t b2_off = (uint32_t)(((wn2 * 32 + (lane & 7) + (lane >> 4) * 8) * VSTR
                                       + ((lane >> 3) & 1) * 8) * 2);

    float c2[4][4];
    #pragma unroll
    for (int nt = 0; nt < 4; nt++)
        #pragma unroll
        for (int i = 0; i < 4; i++) c2[nt][i] = 0.f;

    for (int ch = 0; ch < 2; ch++) {
        if (ch == 1) {
            __syncthreads();
            #pragma unroll
            for (int i = 0; i < 8; i++) {
                int t = tid + i * 256;
                int f = t >> 5, g = t & 31;
                cp16(sb + VH_OFF + (f * VSTR + g * 8) * 2,
                     vth + ((long)bh * DH_ + f) * L_ + 256 + g * 8);
            }
            #pragma unroll
            for (int i = 0; i < 8; i++) {
                int t = tid + i * 256;
                int f = t >> 5, g = t & 31;
                cp16(sb + VL_OFF + (f * VSTR + g * 8) * 2,
                     vtl + ((long)bh * DH_ + f) * L_ + 256 + g * 8);
            }
            CP_COMMIT();
            CP_WAIT(0);
            __syncthreads();
        }
        const uint32_t pko = (uint32_t)(ch * 256 * 2);
        #pragma unroll
        for (int kk = 0; kk < 16; kk++) {
            const uint32_t ko = kk * 32;
            uint32_t pH[4], pL[4];
            LDSM_X4(pH[0], pH[1], pH[2], pH[3], sb + PH_OFF + a2_off + pko + ko);
            LDSM_X4(pL[0], pL[1], pL[2], pL[3], sb + PL_OFF + a2_off + pko + ko);
            uint32_t Bh2[8], Bl2[8];
            #pragma unroll
            for (int p = 0; p < 2; p++) {
                LDSM_X4(Bh2[p*4+0], Bh2[p*4+1], Bh2[p*4+2], Bh2[p*4+3], sb + VH_OFF + b2_off + p * (16*VSTR*2) + ko);
                LDSM_X4(Bl2[p*4+0], Bl2[p*4+1], Bl2[p*4+2], Bl2[p*4+3], sb + VL_OFF + b2_off + p * (16*VSTR*2) + ko);
            }
            #pragma unroll
            for (int nt = 0; nt < 4; nt++) {
                const int bi = (nt >> 1) * 4 + (nt & 1) * 2;
                mma_bf16(c2[nt], pL, Bh2[bi], Bh2[bi+1]);
                mma_bf16(c2[nt], pH, Bl2[bi], Bl2[bi+1]);
                mma_bf16(c2[nt], pH, Bh2[bi], Bh2[bi+1]);
            }
        }
    }

    #pragma unroll
    for (int nt = 0; nt < 4; nt++) {
        #pragma unroll
        for (int half = 0; half < 2; half++) {
            const int row = q0 + wm2 * 16 + gid + half * 8;
            const int col = head * DH_ + wn2 * 32 + nt * 8 + tq * 2;
            uint32_t hi, lo;
            split2(c2[nt][half * 2 + 0], c2[nt][half * 2 + 1], hi, lo);
            const long o = ((long)b * L_ + row) * D_ + col;
            *(uint32_t*)&ctxh[o] = hi;
            *(uint32_t*)&ctxl[o] = lo;
        }
    }
}

// ---------------- V^T materialization ----------------
__global__ void vt_transpose(const __nv_bfloat16* __restrict__ qkvh,
                             const __nv_bfloat16* __restrict__ qkvl,
                             __nv_bfloat16* __restrict__ vth, __nv_bfloat16* __restrict__ vtl)
{
    __shared__ uint16_t th[32][33], tl[32][33];
    const int bh = blockIdx.z;
    const int b = bh / H_, head = bh % H_;
    const int s0 = blockIdx.x * 32;
    const int f0 = blockIdx.y * 32;
    const int tx = threadIdx.x, ty = threadIdx.y;
    const long src = (long)b * L_ * TD_ + 2 * D_ + head * DH_;
    #pragma unroll
    for (int i = 0; i < 32; i += 8) {
        th[ty + i][tx] = ((const uint16_t*)qkvh)[src + (long)(s0 + ty + i) * TD_ + f0 + tx];
        tl[ty + i][tx] = ((const uint16_t*)qkvl)[src + (long)(s0 + ty + i) * TD_ + f0 + tx];
    }
    __syncthreads();
    const long dst = ((long)bh * DH_ + f0) * L_ + s0;
    #pragma unroll
    for (int i = 0; i < 32; i += 8) {
        ((uint16_t*)vth)[dst + (long)(ty + i) * L_ + tx] = th[tx][ty + i];
        ((uint16_t*)vtl)[dst + (long)(ty + i) * L_ + tx] = tl[tx][ty + i];
    }
}

// ---------------- sparse GCN aggregation (agg1: gelu -> splits) ----------------
__global__ __launch_bounds__(256, 4)
void gcn_agg(const float* __restrict__ xw, const float* __restrict__ dinv,
             const int* __restrict__ start, const int* __restrict__ esrc,
             const float* __restrict__ ew, const float* __restrict__ bias,
             __nv_bfloat16* __restrict__ oh, __nv_bfloat16* __restrict__ ol)
{
    const int b  = blockIdx.x >> 6;
    const int dg = blockIdx.x & 63;
    const int wid = threadIdx.x >> 5, lane = threadIdx.x & 31;
    const int d = dg * 8 + wid;

    const float* xb = xw + (long)b * L_ * D_;
    float acc[24];
    #pragma unroll
    for (int j = 0; j < 24; j++) acc[j] = 0.f;

    const int s0 = start[b * (L_ + 1) + d];
    const int s1 = start[b * (L_ + 1) + d + 1];
    const int*   es = esrc + (long)b * E_;
    const float* we = ew   + (long)b * E_;

    for (int i = s0; i < s1; i++) {
        const int   s = es[i];
        const float w = we[i];
        const float* xr = xb + (long)s * D_ + lane;
        #pragma unroll
        for (int j = 0; j < 24; j++) acc[j] = fmaf(w, xr[32 * j], acc[j]);
    }
    {
        const float di = dinv[b * L_ + d];
        const float w = di * di;
        const float* xr = xb + (long)d * D_ + lane;
        #pragma unroll
        for (int j = 0; j < 24; j++) acc[j] = fmaf(w, xr[32 * j], acc[j]);
    }

    const long rbase = ((long)b * L_ + d) * D_;
    #pragma unroll
    for (int j = 0; j < 24; j++) {
        const int f = lane + 32 * j;
        const float v = gelu_f(acc[j] + bias[f]);
        __nv_bfloat16 hb = __float2bfloat16_rn(v);
        oh[rbase + f] = hb;
        ol[rbase + f] = __float2bfloat16_rn(v - __bfloat162float(hb));
    }
}

// ---------------- agg2 + fused n2-LayerNorm: yh/yl = LN(gelu(agg + bias); gam, bet) ----
__global__ __launch_bounds__(256, 4)
void gcn_agg_ln(const float* __restrict__ xw, const float* __restrict__ dinv,
                const int* __restrict__ start, const int* __restrict__ esrc,
                const float* __restrict__ ew, const float* __restrict__ bias,
                const float* __restrict__ gam, const float* __restrict__ bet,
                __nv_bfloat16* __restrict__ oh, __nv_bfloat16* __restrict__ ol)
{
    const int b  = blockIdx.x >> 6;
    const int dg = blockIdx.x & 63;
    const int wid = threadIdx.x >> 5, lane = threadIdx.x & 31;
    const int d = dg * 8 + wid;

    const float* xb = xw + (long)b * L_ * D_;
    float acc[24];
    #pragma unroll
    for (int j = 0; j < 24; j++) acc[j] = 0.f;

    const int s0 = start[b * (L_ + 1) + d];
    const int s1 = start[b * (L_ + 1) + d + 1];
    const int*   es = esrc + (long)b * E_;
    const float* we = ew   + (long)b * E_;

    for (int i = s0; i < s1; i++) {
        const int   s = es[i];
        const float w = we[i];
        const float* xr = xb + (long)s * D_ + lane;
        #pragma unroll
        for (int j = 0; j < 24; j++) acc[j] = fmaf(w, xr[32 * j], acc[j]);
    }
    {
        const float di = dinv[b * L_ + d];
        const float w = di * di;
        const float* xr = xb + (long)d * D_ + lane;
        #pragma unroll
        for (int j = 0; j < 24; j++) acc[j] = fmaf(w, xr[32 * j], acc[j]);
    }

    // gelu
    #pragma unroll
    for (int j = 0; j < 24; j++)
        acc[j] = gelu_f(acc[j] + bias[lane + 32 * j]);

    // warp LayerNorm over 768 features
    float s = 0.f;
    #pragma unroll
    for (int j = 0; j < 24; j++) s += acc[j];
    #pragma unroll
    for (int o = 16; o > 0; o >>= 1) s += __shfl_xor_sync(0xffffffffu, s, o);
    const float mean = s * (1.f / 768.f);

    float q = 0.f;
    #pragma unroll
    for (int j = 0; j < 24; j++) {
        acc[j] -= mean;
        q += acc[j] * acc[j];
    }
    #pragma unroll
    for (int o = 16; o > 0; o >>= 1) q += __shfl_xor_sync(0xffffffffu, q, o);
    const float r = rsqrtf(q * (1.f / 768.f) + 1e-12f);

    const long rbase = ((long)b * L_ + d) * D_;
    #pragma unroll
    for (int j = 0; j < 24; j++) {
        const int f = lane + 32 * j;
        const float v = acc[j] * r * gam[f] + bet[f];
        __nv_bfloat16 hb = __float2bfloat16_rn(v);
        oh[rbase + f] = hb;
        ol[rbase + f] = __float2bfloat16_rn(v - __bfloat162float(hb));
    }
}

// ---------------- CSR build ----------------
__global__ void csr_count(const int* __restrict__ edges, int* __restrict__ cnt)
{
    const int i = blockIdx.x * 256 + threadIdx.x;
    const int b = i / E_, e = i % E_;
    const int d = edges[(long)b * 2 * E_ + E_ + e];
    atomicAdd(&cnt[b * L_ + d], 1);
}

__global__ void csr_scan(const int* __restrict__ cnt, int* __restrict__ start)
{
    __shared__ int s[L_];
    const int b = blockIdx.x, t = threadIdx.x;
    s[t] = cnt[b * L_ + t];
    for (int off = 1; off < L_; off <<= 1) {
        __syncthreads();
        int v = (t >= off) ? s[t - off] : 0;
        __syncthreads();
        s[t] += v;
    }
    __syncthreads();
    start[b * (L_ + 1) + t + 1] = s[t];
    if (t == 0) start[b * (L_ + 1)] = 0;
}

__global__ void csr_fill(const int* __restrict__ edges, const float* __restrict__ dinv,
                         const int* __restrict__ start, int* __restrict__ cur,
                         int* __restrict__ esrc, float* __restrict__ ew)
{
    const int i = blockIdx.x * 256 + threadIdx.x;
    const int b = i / E_, e = i % E_;
    const int s = edges[(long)b * 2 * E_ + e];
    const int d = edges[(long)b * 2 * E_ + E_ + e];
    const int pos = start[b * (L_ + 1) + d] + atomicAdd(&cur[b * L_ + d], 1);
    esrc[(long)b * E_ + pos] = s;
    ew  [(long)b * E_ + pos] = dinv[b * L_ + s] * dinv[b * L_ + d];
}

// ---------------- split transpose (weights prep) ----------------
__global__ void transpose_split(const float* __restrict__ in,
                                __nv_bfloat16* __restrict__ outh,
                                __nv_bfloat16* __restrict__ outl,
                                int R, int C)
{
    __shared__ float t[32][33];
    const long z = blockIdx.z;
    in   += z * (long)R * C;
    outh += z * (long)R * C;
    outl += z * (long)R * C;
    const int c0 = blockIdx.x * 32, r0 = blockIdx.y * 32;
    const int tx = threadIdx.x, ty = threadIdx.y;
    #pragma unroll
    for (int i = 0; i < 32; i += 8)
        t[ty + i][tx] = in[(long)(r0 + ty + i) * C + c0 + tx];
    __syncthreads();
    #pragma unroll
    for (int i = 0; i < 32; i += 8) {
        float v = t[tx][ty + i];
        __nv_bfloat16 hb = __float2bfloat16_rn(v);
        float lo = v - __bfloat162float(hb);
        const long o = (long)(c0 + ty + i) * R + r0 + tx;
        outh[o] = hb;
        outl[o] = __float2bfloat16_rn(lo);
    }
}

// ---------------- split copy ----------------
__global__ void split_copy(const float* __restrict__ in,
                           __nv_bfloat16* __restrict__ oh, __nv_bfloat16* __restrict__ ol,
                           int n4)
{
    const int i = blockIdx.x * 256 + threadIdx.x;
    if (i >= n4) return;
    float4 v = ((const float4*)in)[i];
    uint32_t h0, l0, h1, l1;
    split2(v.x, v.y, h0, l0);
    split2(v.z, v.w, h1, l1);
    ((uint2*)oh)[i] = make_uint2(h0, h1);
    ((uint2*)ol)[i] = make_uint2(l0, l1);
}

// ---------------- bias-pair gather ----------------
__global__ void bias2_gather(const float* __restrict__ m3b, const float* __restrict__ m1b,
                             float* __restrict__ out)
{
    const int i = blockIdx.x * 256 + threadIdx.x;
    if (i >= NL_ * 2 * D_) return;
    const int l = i / (2 * D_), j = i % (2 * D_);
    out[i] = (j < D_) ? m3b[l * D_ + j] : m1b[l * D_ + j - D_];
}

// ---------------- LayerNorm ----------------
__global__ void ln_kernel(const float* __restrict__ in,
                          const float* __restrict__ gam,
                          const float* __restrict__ bet,
                          float* __restrict__ out,
                          __nv_bfloat16* __restrict__ outh,
                          __nv_bfloat16* __restrict__ outl)
{
    __shared__ float red[8];
    const int row = blockIdx.x;
    const int t = threadIdx.x;
    const int lane = t & 31, w = t >> 5;
    const float* xp = in + (long)row * D_;

    float v0 = xp[t], v1 = xp[t + 256], v2 = xp[t + 512];
    float s = v0 + v1 + v2;
    #pragma unroll
    for (int o = 16; o > 0; o >>= 1) s += __shfl_xor_sync(0xffffffffu, s, o);
    if (lane == 0) red[w] = s;
    __syncthreads();
    s = 0.f;
    #pragma unroll
    for (int i = 0; i < 8; i++) s += red[i];
    const float mean = s * (1.f / 768.f);
    __syncthreads();

    float d0 = v0 - mean, d1 = v1 - mean, d2 = v2 - mean;
    float q = d0 * d0 + d1 * d1 + d2 * d2;
    #pragma unroll
    for (int o = 16; o > 0; o >>= 1) q += __shfl_xor_sync(0xffffffffu, q, o);
    if (lane == 0) red[w] = q;
    __syncthreads();
    q = 0.f;
    #pragma unroll
    for (int i = 0; i < 8; i++) q += red[i];
    const float r = rsqrtf(q * (1.f / 768.f) + 1e-12f);

    const float o0 = d0 * r * gam[t]       + bet[t];
    const float o1 = d1 * r * gam[t + 256] + bet[t + 256];
    const float o2 = d2 * r * gam[t + 512] + bet[t + 512];
    if (out) {
        float* op = out + (long)row * D_;
        op[t] = o0; op[t + 256] = o1; op[t + 512] = o2;
    }
    if (outh) {
        __nv_bfloat16* oph = outh + (long)row * D_;
        __nv_bfloat16* opl = outl + (long)row * D_;
        __nv_bfloat16 h0 = __float2bfloat16_rn(o0);
        __nv_bfloat16 h1 = __float2bfloat16_rn(o1);
        __nv_bfloat16 h2 = __float2bfloat16_rn(o2);
        oph[t] = h0;       opl[t]       = __float2bfloat16_rn(o0 - __bfloat162float(h0));
        oph[t + 256] = h1; opl[t + 256] = __float2bfloat16_rn(o1 - __bfloat162float(h1));
        oph[t + 512] = h2; opl[t + 512] = __float2bfloat16_rn(o2 - __bfloat162float(h2));
    }
}

// ---------------- fused dual LayerNorm ----------------
__global__ void ln_dual_kernel(const float* __restrict__ in,
                               const float* __restrict__ g1, const float* __restrict__ b1,
                               const float* __restrict__ g2, const float* __restrict__ b2,
                               float* __restrict__ h1out,
                               __nv_bfloat16* __restrict__ s0h, __nv_bfloat16* __restrict__ s0l,
                               __nv_bfloat16* __restrict__ s1h, __nv_bfloat16* __restrict__ s1l)
{
    __shared__ float red[8];
    const int row = blockIdx.x;
    const int t = threadIdx.x;
    const int lane = t & 31, w = t >> 5;
    const float* xp = in + (long)row * D_;

    float v0 = xp[t], v1 = xp[t + 256], v2 = xp[t + 512];
    float s = v0 + v1 + v2;
    #pragma unroll
    for (int o = 16; o > 0; o >>= 1) s += __shfl_xor_sync(0xffffffffu, s, o);
    if (lane == 0) red[w] = s;
    __syncthreads();
    s = 0.f;
    #pragma unroll
    for (int i = 0; i < 8; i++) s += red[i];
    const float mean = s * (1.f / 768.f);
    __syncthreads();

    float d0 = v0 - mean, d1 = v1 - mean, d2 = v2 - mean;
    float q = d0 * d0 + d1 * d1 + d2 * d2;
    #pragma unroll
    for (int o = 16; o > 0; o >>= 1) q += __shfl_xor_sync(0xffffffffu, q, o);
    if (lane == 0) red[w] = q;
    __syncthreads();
    q = 0.f;
    #pragma unroll
    for (int i = 0; i < 8; i++) q += red[i];
    const float r = rsqrtf(q * (1.f / 768.f) + 1e-12f);

    const float o0 = d0 * r * g1[t]       + b1[t];
    const float o1 = d1 * r * g1[t + 256] + b1[t + 256];
    const float o2 = d2 * r * g1[t + 512] + b1[t + 512];
    {
        float* op = h1out + (long)row * D_;
        op[t] = o0; op[t + 256] = o1; op[t + 512] = o2;
        __nv_bfloat16* oph = s0h + (long)row * D_;
        __nv_bfloat16* opl = s0l + (long)row * D_;
        __nv_bfloat16 h0 = __float2bfloat16_rn(o0);
        __nv_bfloat16 h1 = __float2bfloat16_rn(o1);
        __nv_bfloat16 h2 = __float2bfloat16_rn(o2);
        oph[t] = h0;       opl[t]       = __float2bfloat16_rn(o0 - __bfloat162float(h0));
        oph[t + 256] = h1; opl[t + 256] = __float2bfloat16_rn(o1 - __bfloat162float(h1));
        oph[t + 512] = h2; opl[t + 512] = __float2bfloat16_rn(o2 - __bfloat162float(h2));
    }

    __syncthreads();
    float s2 = o0 + o1 + o2;
    #pragma unroll
    for (int o = 16; o > 0; o >>= 1) s2 += __shfl_xor_sync(0xffffffffu, s2, o);
    if (lane == 0) red[w] = s2;
    __syncthreads();
    s2 = 0.f;
    #pragma unroll
    for (int i = 0; i < 8; i++) s2 += red[i];
    const float mean2 = s2 * (1.f / 768.f);
    __syncthreads();

    float e0 = o0 - mean2, e1 = o1 - mean2, e2 = o2 - mean2;
    float q2 = e0 * e0 + e1 * e1 + e2 * e2;
    #pragma unroll
    for (int o = 16; o > 0; o >>= 1) q2 += __shfl_xor_sync(0xffffffffu, q2, o);
    if (lane == 0) red[w] = q2;
    __syncthreads();
    q2 = 0.f;
    #pragma unroll
    for (int i = 0; i < 8; i++) q2 += red[i];
    const float r2 = rsqrtf(q2 * (1.f / 768.f) + 1e-12f);

    const float p0 = e0 * r2 * g2[t]       + b2[t];
    const float p1 = e1 * r2 * g2[t + 256] + b2[t + 256];
    const float p2 = e2 * r2 * g2[t + 512] + b2[t + 512];
    {
        __nv_bfloat16* oph = s1h + (long)row * D_;
        __nv_bfloat16* opl = s1l + (long)row * D_;
        __nv_bfloat16 h0 = __float2bfloat16_rn(p0);
        __nv_bfloat16 h1 = __float2bfloat16_rn(p1);
        __nv_bfloat16 h2 = __float2bfloat16_rn(p2);
        oph[t] = h0;       opl[t]       = __float2bfloat16_rn(p0 - __bfloat162float(h0));
        oph[t + 256] = h1; opl[t + 256] = __float2bfloat16_rn(p1 - __bfloat162float(h1));
        oph[t + 512] = h2; opl[t + 512] = __float2bfloat16_rn(p2 - __bfloat162float(h2));
    }
}

// ---------------- degree ----------------
__global__ void deg_kernel(const int* __restrict__ edges, float* __restrict__ dinv)
{
    __shared__ float sdeg[L_];
    const int b = blockIdx.x, t = threadIdx.x;
    sdeg[t] = 1.f;
    __syncthreads();
    const int* dst = edges + (long)b * 2 * E_ + E_;
    for (int e = t; e < E_; e += L_) atomicAdd(&sdeg[dst[e]], 1.f);
    __syncthreads();
    dinv[b * L_ + t] = rsqrtf(sdeg[t]);
}

// ---------------- host side ----------------
static void launch_mma(int epi, int tn,
                       const __nv_bfloat16* Ah, const __nv_bfloat16* Al,
                       const __nv_bfloat16* Bh, const __nv_bfloat16* Bl,
                       const float* bias, const float* add,
                       float* C, __nv_bfloat16* Ch, __nv_bfloat16* Cl,
                       int Mr, int N, int K, int batch,
                       long sA, long sB, long sC, long sBias = 0)
{
    dim3 grid(N / tn, Mr / TM_T, batch), block(256);
    if (tn == 256) {
        switch (epi) {
            case 0: mma_gemm<0,256><<<grid, block, SMEM_MMA(256)>>>(Ah, Al, Bh, Bl, bias, add, C, Ch, Cl, K, N, sA, sB, sC, sBias); break;
            case 1: mma_gemm<1,256><<<grid, block, SMEM_MMA(256)>>>(Ah, Al, Bh, Bl, bias, add, C, Ch, Cl, K, N, sA, sB, sC, sBias); break;
            case 2: mma_gemm<2,256><<<grid, block, SMEM_MMA(256)>>>(Ah, Al, Bh, Bl, bias, add, C, Ch, Cl, K, N, sA, sB, sC, sBias); break;
            case 3: mma_gemm<3,256><<<grid, block, SMEM_MMA(256)>>>(Ah, Al, Bh, Bl, bias, add, C, Ch, Cl, K, N, sA, sB, sC, sBias); break;
        }
    } else {
        switch (epi) {
            case 0: mma_gemm<0,192><<<grid, block, SMEM_MMA(192)>>>(Ah, Al, Bh, Bl, bias, add, C, Ch, Cl, K, N, sA, sB, sC, sBias); break;
            case 1: mma_gemm<1,192><<<grid, block, SMEM_MMA(192)>>>(Ah, Al, Bh, Bl, bias, add, C, Ch, Cl, K, N, sA, sB, sC, sBias); break;
            case 2: mma_gemm<2,192><<<grid, block, SMEM_MMA(192)>>>(Ah, Al, Bh, Bl, bias, add, C, Ch, Cl, K, N, sA, sB, sC, sBias); break;
            case 3: mma_gemm<3,192><<<grid, block, SMEM_MMA(192)>>>(Ah, Al, Bh, Bl, bias, add, C, Ch, Cl, K, N, sA, sB, sC, sBias); break;
        }
    }
}

extern "C" void kernel_launch(void* const* d_in, const int* in_sizes, int n_in,
                              void* d_out, int out_size)
{
    const float* hidden = (const float*)d_in[0];
    const int*   edges  = (const int*)  d_in[1];
    const float* Wqkv   = (const float*)d_in[2];
    const float* bqkv   = (const float*)d_in[3];
    const float* Wo     = (const float*)d_in[4];
    const float* bo     = (const float*)d_in[5];
    const float* ln1_s  = (const float*)d_in[6];
    const float* ln1_b  = (const float*)d_in[7];
    const float* n1_s   = (const float*)d_in[8];
    const float* n1_b   = (const float*)d_in[9];
    const float* m1_W   = (const float*)d_in[10];
    const float* m1_b   = (const float*)d_in[11];
    const float* c1_W   = (const float*)d_in[12];
    const float* c1_b   = (const float*)d_in[13];
    const float* c2_W   = (const float*)d_in[14];
    const float* c2_b   = (const float*)d_in[15];
    const float* n2_s   = (const float*)d_in[16];
    const float* n2_b   = (const float*)d_in[17];
    const float* m2_W   = (const float*)d_in[18];
    const float* m2_b   = (const float*)d_in[19];
    const float* m3_W   = (const float*)d_in[20];
    const float* m3_b   = (const float*)d_in[21];
    const float* int_W  = (const float*)d_in[22];
    const float* int_b  = (const float*)d_in[23];
    const float* out_W  = (const float*)d_in[24];
    const float* out_b  = (const float*)d_in[25];
    const float* ln2_s  = (const float*)d_in[26];
    const float* ln2_b  = (const float*)d_in[27];

    float *h, *h1, *y, *gg, *dinv, *pairC, *bias2, *ew;
    int *cnt, *startp, *cur, *esrc;
    __nv_bfloat16 *hh, *hl, *qkvh, *qkvl, *vth, *vtl, *ctxh, *ctxl,
                  *pairAh, *pairAl, *pairCh, *pairCl,
                  *xh, *xl, *yh, *yl, *ggh, *ggl, *midh, *midl, *wTh, *wTl;
    cudaGetSymbolAddress((void**)&h,    g_h);
    cudaGetSymbolAddress((void**)&h1,   g_h1);
    cudaGetSymbolAddress((void**)&y,    g_y);
    cudaGetSymbolAddress((void**)&gg,   g_g);
    cudaGetSymbolAddress((void**)&dinv, g_dinv);
    cudaGetSymbolAddress((void**)&pairC, g_pairC);
    cudaGetSymbolAddress((void**)&bias2, g_bias2);
    cudaGetSymbolAddress((void**)&cnt,   g_cnt);
    cudaGetSymbolAddress((void**)&startp, g_start);
    cudaGetSymbolAddress((void**)&cur,   g_cur);
    cudaGetSymbolAddress((void**)&esrc,  g_esrc);
    cudaGetSymbolAddress((void**)&ew,    g_ew);
    cudaGetSymbolAddress((void**)&hh,   g_hh);   cudaGetSymbolAddress((void**)&hl,   g_hl);
    cudaGetSymbolAddress((void**)&qkvh, g_qkvh); cudaGetSymbolAddress((void**)&qkvl, g_qkvl);
    cudaGetSymbolAddress((void**)&vth,  g_vth);  cudaGetSymbolAddress((void**)&vtl,  g_vtl);
    cudaGetSymbolAddress((void**)&ctxh, g_ctxh); cudaGetSymbolAddress((void**)&ctxl, g_ctxl);
    cudaGetSymbolAddress((void**)&pairAh, g_pairAh); cudaGetSymbolAddress((void**)&pairAl, g_pairAl);
    cudaGetSymbolAddress((void**)&pairCh, g_pairCh); cudaGetSymbolAddress((void**)&pairCl, g_pairCl);
    cudaGetSymbolAddress((void**)&xh,   g_xh);   cudaGetSymbolAddress((void**)&xl,   g_xl);
    cudaGetSymbolAddress((void**)&yh,   g_yh);   cudaGetSymbolAddress((void**)&yl,   g_yl);
    cudaGetSymbolAddress((void**)&ggh,  g_ggh);  cudaGetSymbolAddress((void**)&ggl,  g_ggl);
    cudaGetSymbolAddress((void**)&midh, g_midh); cudaGetSymbolAddress((void**)&midl, g_midl);
    cudaGetSymbolAddress((void**)&wTh,  g_wTh);  cudaGetSymbolAddress((void**)&wTl,  g_wTl);

    cudaFuncSetAttribute(mma_gemm<0,256>, cudaFuncAttributeMaxDynamicSharedMemorySize, SMEM_MMA(256));
    cudaFuncSetAttribute(mma_gemm<1,256>, cudaFuncAttributeMaxDynamicSharedMemorySize, SMEM_MMA(256));
    cudaFuncSetAttribute(mma_gemm<2,256>, cudaFuncAttributeMaxDynamicSharedMemorySize, SMEM_MMA(256));
    cudaFuncSetAttribute(mma_gemm<3,256>, cudaFuncAttributeMaxDynamicSharedMemorySize, SMEM_MMA(256));
    cudaFuncSetAttribute(mma_gemm<0,192>, cudaFuncAttributeMaxDynamicSharedMemorySize, SMEM_MMA(192));
    cudaFuncSetAttribute(mma_gemm<1,192>, cudaFuncAttributeMaxDynamicSharedMemorySize, SMEM_MMA(192));
    cudaFuncSetAttribute(mma_gemm<2,192>, cudaFuncAttributeMaxDynamicSharedMemorySize, SMEM_MMA(192));
    cudaFuncSetAttribute(mma_gemm<3,192>, cudaFuncAttributeMaxDynamicSharedMemorySize, SMEM_MMA(192));
    cudaFuncSetAttribute(attn_fused, cudaFuncAttributeMaxDynamicSharedMemorySize, SMEM_ATT);

    // setup: hidden copy + split, graph structure (CSR), bias pairs
    cudaMemcpyAsync(h, hidden, sizeof(float) * M_ * D_, cudaMemcpyDeviceToDevice);
    split_copy<<<(M_ * D_ / 4 + 255) / 256, 256>>>(hidden, hh, hl, M_ * D_ / 4);
    deg_kernel<<<B_, L_>>>(edges, dinv);
    cudaMemsetAsync(cnt, 0, sizeof(int) * B_ * L_);
    cudaMemsetAsync(cur, 0, sizeof(int) * B_ * L_);
    csr_count<<<(B_ * E_) / 256, 256>>>(edges, cnt);
    csr_scan<<<B_, L_>>>(cnt, startp);
    csr_fill<<<(B_ * E_) / 256, 256>>>(edges, dinv, startp, cur, esrc, ew);
    bias2_gather<<<(NL_ * 2 * D_ + 255) / 256, 256>>>(m3_b, m1_b, bias2);

    dim3 tb(32, 8);
    transpose_split<<<dim3(TD_/32, D_/32, NL_), tb>>>(Wqkv, wTh + OFF_QKV, wTl + OFF_QKV, D_, TD_);
    transpose_split<<<dim3(D_/32,  D_/32, NL_), tb>>>(Wo,   wTh + OFF_WO,  wTl + OFF_WO,  D_, D_);
    transpose_split<<<dim3(D_/32,  D_/32, NL_), tb>>>(m1_W, wTh + OFF_M1,  wTl + OFF_M1,  D_, D_);
    transpose_split<<<dim3(D_/32,  D_/32, NL_), tb>>>(c1_W, wTh + OFF_C1,  wTl + OFF_C1,  D_, D_);
    transpose_split<<<dim3(D_/32,  D_/32, NL_), tb>>>(c2_W, wTh + OFF_C2,  wTl + OFF_C2,  D_, D_);
    transpose_split<<<dim3(D_/32,  D_/32, NL_), tb>>>(m2_W, wTh + OFF_M2,  wTl + OFF_M2,  D_, D_);
    transpose_split<<<dim3(D_/32,  D_/32, NL_), tb>>>(m3_W, wTh + OFF_M3,  wTl + OFF_M3,  D_, D_);
    transpose_split<<<dim3(DF_/32, D_/32, NL_), tb>>>(int_W, wTh + OFF_INT, wTl + OFF_INT, D_, DF_);
    transpose_split<<<dim3(D_/32,  DF_/32, NL_), tb>>>(out_W, wTh + OFF_OUT, wTl + OFF_OUT, DF_, D_);

    const long MD = (long)M_ * D_;

    for (int l = 0; l < NL_; l++) {
        const long oQ = OFF_QKV + (long)l * TD_ * D_;
        const long oW = OFF_WO  + (long)l * D_ * D_;
        const long oc1 = OFF_C1 + (long)l * D_ * D_;
        const long oc2 = OFF_C2 + (long)l * D_ * D_;
        const long o2 = OFF_M2  + (long)l * D_ * D_;
        const long o3 = OFF_M3  + (long)l * D_ * D_;
        const long oi = OFF_INT + (long)l * DF_ * D_;
        const long oo = OFF_OUT + (long)l * D_ * DF_;

        const float* bqkv_l = bqkv + (long)l * TD_;
        const float* bo_l   = bo   + (long)l * D_;
        const float* ln1s = ln1_s + (long)l * D_;
        const float* ln1b = ln1_b + (long)l * D_;
        const float* n1s  = n1_s + (long)l * D_;
        const float* n1b  = n1_b + (long)l * D_;
        const float* c1b  = c1_b + (long)l * D_;
        const float* c2b  = c2_b + (long)l * D_;
        const float* n2s  = n2_s + (long)l * D_;
        const float* n2b  = n2_b + (long)l * D_;
        const float* m2b  = m2_b + (long)l * D_;
        const float* intb = int_b + (long)l * DF_;
        const float* outb = out_b + (long)l * D_;
        const float* ln2s = ln2_s + (long)l * D_;
        const float* ln2b = ln2_b + (long)l * D_;

        // qkv = h @ Wqkv + b  (packed coalesced split stores)
        launch_mma(0, 256, hh, hl, wTh + oQ, wTl + oQ, bqkv_l, 0, 0, qkvh, qkvl, M_, TD_, D_, 1, 0, 0, 0);
        // attention (fused scores+softmax+ctx; P stays in smem)
        vt_transpose<<<dim3(L_/32, DH_/32, BH_), tb>>>(qkvh, qkvl, vth, vtl);
        attn_fused<<<dim3(BH_, L_ / 64), 256, SMEM_ATT>>>(qkvh, qkvl, vth, vtl, ctxh, ctxl);
        // h1 = LN(ctx @ Wo + bo + h); fused second LN(n1)
        launch_mma(1, 192, ctxh, ctxl, wTh + oW, wTl + oW, bo_l, h, y, 0, 0, M_, D_, D_, 1, 0, 0, 0);
        ln_dual_kernel<<<M_, 256>>>(y, ln1s, ln1b, n1s, n1b, h1,
                                    pairAh, pairAl, pairAh + MD, pairAl + MD);
        // batched pair: z0 res = gelu(h1@m3+b3); z1 x = gelu(LN@m1+b1)
        launch_mma(2, 192, pairAh, pairAl, wTh + o3, wTl + o3, bias2 + (long)l * 2 * D_, 0,
                   pairC, pairCh, pairCl, M_, D_, D_, 2, MD, OFF_M1 - OFF_M3, MD, D_);
        // GCN 1: y = x @ c1W (fp32); x = gelu(gather(y) + c1b) -> splits
        launch_mma(0, 192, pairCh + MD, pairCl + MD, wTh + oc1, wTl + oc1, 0, 0, y, 0, 0, M_, D_, D_, 1, 0, 0, 0);
        gcn_agg<<<B_ * 64, 256>>>(y, dinv, startp, esrc, ew, c1b, xh, xl);
        // GCN 2: y = x @ c2W (fp32); yh/yl = LN(gelu(gather(y) + c2b); n2)   [fused]
        launch_mma(0, 192, xh, xl, wTh + oc2, wTl + oc2, 0, 0, y, 0, 0, M_, D_, D_, 1, 0, 0, 0);
        gcn_agg_ln<<<B_ * 64, 256>>>(y, dinv, startp, esrc, ew, c2b, n2s, n2b, yh, yl);
        // g = res + gelu(LN @ m2 + b)
        launch_mma(3, 192, yh, yl, wTh + o2, wTl + o2, m2b, pairC, gg, ggh, ggl, M_, D_, D_, 1, 0, 0, 0);
        // FFN
        launch_mma(2, 256, ggh, ggl, wTh + oi, wTl + oi, intb, 0, 0, midh, midl, M_, DF_, D_, 1, 0, 0, 0);
        launch_mma(1, 192, midh, midl, wTh + oo, wTl + oo, outb, gg, y, 0, 0, M_, D_, DF_, 1, 0, 0, 0);
        if (l == NL_ - 1)
            ln_kernel<<<M_, 256>>>(y, ln2s, ln2b, (float*)d_out, 0, 0);
        else
            ln_kernel<<<M_, 256>>>(y, ln2s, ln2b, h, hh, hl);
    }
}